// round 10
// baseline (speedup 1.0000x reference)
#include <cuda_runtime.h>
#include <cuda_bf16.h>
#include <math.h>
#include <stdint.h>

// ---------------- Problem constants ----------------
#define S    2048
#define D    1024
#define NH   16
#define HD   64
#define HFF  2816
#define NV   32000
#define NL   4

typedef __nv_bfloat16 bf16;

// ---------------- Device scratch ----------------
__device__ float g_h[S * D];
__device__ float g_cos[S * 32];
__device__ float g_sin[S * 32];
__device__ float g_xf[D];

__device__ __align__(16) bf16 g_xh[S * D],  g_xl[S * D];
__device__ __align__(16) bf16 g_oh[S * D],  g_ol[S * D];
__device__ __align__(16) bf16 g_gh[S * HFF], g_gl[S * HFF];
__device__ __align__(16) bf16 g_qh[S * D], g_ql[S * D];
__device__ __align__(16) bf16 g_kh[S * D], g_kl[S * D];
__device__ __align__(16) bf16 g_vh[S * D], g_vl[S * D];

__device__ __align__(16) bf16 g_wqkvh[NL * D * 3 * D], g_wqkvl[NL * D * 3 * D];
__device__ __align__(16) bf16 g_w13h[NL * D * 2 * HFF], g_w13l[NL * D * 2 * HFF];
__device__ __align__(16) bf16 g_woh[NL * D * D], g_wol[NL * D * D];
__device__ __align__(16) bf16 g_w2h[NL * HFF * D], g_w2l[NL * HFF * D];

// ---------------- small helpers ----------------
__device__ __forceinline__ void split1(float v, bf16& h, bf16& l) {
    h = __float2bfloat16(v);
    l = __float2bfloat16(v - __bfloat162float(h));
}
__device__ __forceinline__ void split2pack(float x, float y, unsigned& hp, unsigned& lp) {
    bf16 hx = __float2bfloat16(x), hy = __float2bfloat16(y);
    float lx = x - __bfloat162float(hx), ly = y - __bfloat162float(hy);
    bf16 lxb = __float2bfloat16(lx), lyb = __float2bfloat16(ly);
    hp = (unsigned)(*(unsigned short*)&hx) | ((unsigned)(*(unsigned short*)&hy) << 16);
    lp = (unsigned)(*(unsigned short*)&lxb) | ((unsigned)(*(unsigned short*)&lyb) << 16);
}

// ---------------- ONE fused pack+split kernel for all weights ----------------
#define PDD (D * D / 2)
#define PDF (D * HFF / 2)
__global__ void pack_all_kernel(
    const float* __restrict__ Wq, const float* __restrict__ Wk, const float* __restrict__ Wv,
    const float* __restrict__ W1, const float* __restrict__ W3,
    const float* __restrict__ Wo, const float* __restrict__ W2,
    bf16* __restrict__ qkvh, bf16* __restrict__ qkvl,
    bf16* __restrict__ w13h, bf16* __restrict__ w13l,
    bf16* __restrict__ woh, bf16* __restrict__ wol,
    bf16* __restrict__ w2h, bf16* __restrict__ w2l) {
    const int l = blockIdx.z;
    long idx = (long)blockIdx.x * 256 + threadIdx.x;

    if (idx < 3L * PDD) {
        int seg = (int)(idx / PDD);
        int r = (int)(idx % PDD);
        const float* src = (seg == 0 ? Wq : seg == 1 ? Wk : Wv) + (size_t)l * D * D;
        int k = r / (D / 2), n = (r % (D / 2)) * 2;
        float2 v = *(const float2*)(src + (size_t)k * D + n);
        unsigned hp, lp; split2pack(v.x, v.y, hp, lp);
        size_t o = (size_t)l * 3 * D * D + (size_t)k * 3 * D + seg * D + n;
        *(unsigned*)(qkvh + o) = hp;
        *(unsigned*)(qkvl + o) = lp;
        return;
    }
    idx -= 3L * PDD;
    if (idx < 2L * PDF) {
        int seg = (int)(idx / PDF);
        int r = (int)(idx % PDF);
        const float* src = (seg == 0 ? W1 : W3) + (size_t)l * D * HFF;
        int k = r / (HFF / 2), n = (r % (HFF / 2)) * 2;
        float2 v = *(const float2*)(src + (size_t)k * HFF + n);
        bf16 h, lo;
        size_t o = (size_t)l * 2 * D * HFF + (size_t)k * 2 * HFF + seg + 2 * n;
        split1(v.x, h, lo); w13h[o] = h; w13l[o] = lo;
        split1(v.y, h, lo); w13h[o + 2] = h; w13l[o + 2] = lo;
        return;
    }
    idx -= 2L * PDF;
    if (idx < PDD) {
        const float* src = Wo + (size_t)l * D * D;
        int k = (int)(idx / (D / 2)), n = (int)(idx % (D / 2)) * 2;
        float2 v = *(const float2*)(src + (size_t)k * D + n);
        unsigned hp, lp; split2pack(v.x, v.y, hp, lp);
        size_t o = (size_t)l * D * D + (size_t)k * D + n;
        *(unsigned*)(woh + o) = hp;
        *(unsigned*)(wol + o) = lp;
        return;
    }
    idx -= PDD;
    {
        const float* src = W2 + (size_t)l * HFF * D;
        int k = (int)(idx / (D / 2)), n = (int)(idx % (D / 2)) * 2;
        float2 v = *(const float2*)(src + (size_t)k * D + n);
        unsigned hp, lp; split2pack(v.x, v.y, hp, lp);
        size_t o = (size_t)l * HFF * D + (size_t)k * D + n;
        *(unsigned*)(w2h + o) = hp;
        *(unsigned*)(w2l + o) = lp;
    }
}
#define PACK_TOTAL (4L * PDD + 3L * PDF)

// ---------------- RoPE table ----------------
__global__ void rope_table_kernel(float* ct, float* st) {
    int idx = blockIdx.x * 256 + threadIdx.x;
    if (idx >= S * 32) return;
    int pos = idx >> 5;
    int i = idx & 31;
    float inv = powf(10000.0f, -((float)(2 * i) / (float)HD));
    float ang = (float)pos * inv;
    float s, c;
    sincosf(ang, &s, &c);
    ct[idx] = c;
    st[idx] = s;
}

// ---------------- Embedding gather ----------------
__global__ void embed_kernel(const int* __restrict__ tokens,
                             const float* __restrict__ emb,
                             float* __restrict__ h) {
    int idx = blockIdx.x * 256 + threadIdx.x;
    int s = idx >> 10;
    int d = idx & 1023;
    h[idx] = emb[(size_t)tokens[s] * D + d];
}

// ---------------- RMSNorm -> split bf16 hi/lo ----------------
__global__ void rmsnorm_split_kernel(const float* __restrict__ in,
                                     const float* __restrict__ w,
                                     bf16* __restrict__ oh, bf16* __restrict__ ol) {
    const float* r = in + (size_t)blockIdx.x * D;
    bf16* ph = oh + (size_t)blockIdx.x * D;
    bf16* pl = ol + (size_t)blockIdx.x * D;
    int t = threadIdx.x;
    float v[4];
    float ss = 0.f;
#pragma unroll
    for (int i = 0; i < 4; i++) { v[i] = r[t + i * 256]; ss += v[i] * v[i]; }
#pragma unroll
    for (int off = 16; off; off >>= 1) ss += __shfl_xor_sync(0xffffffffu, ss, off);
    __shared__ float red[8];
    if ((t & 31) == 0) red[t >> 5] = ss;
    __syncthreads();
    if (t < 8) {
        float x = red[t];
#pragma unroll
        for (int off = 4; off; off >>= 1) x += __shfl_xor_sync(0xffu, x, off);
        if (t == 0) red[0] = x;
    }
    __syncthreads();
    float scale = rsqrtf(red[0] * (1.0f / (float)D) + 1e-6f);
#pragma unroll
    for (int i = 0; i < 4; i++) {
        float rv = v[i] * scale * w[t + i * 256];
        bf16 h, l; split1(rv, h, l);
        ph[t + i * 256] = h;
        pl[t + i * 256] = l;
    }
}

// ---------------- plain fp32 RMSNorm (final row) ----------------
__global__ void rmsnorm_kernel(const float* __restrict__ in,
                               const float* __restrict__ w,
                               float* __restrict__ out) {
    const float* r = in;
    int t = threadIdx.x;
    float v[4];
    float ss = 0.f;
#pragma unroll
    for (int i = 0; i < 4; i++) { v[i] = r[t + i * 256]; ss += v[i] * v[i]; }
#pragma unroll
    for (int off = 16; off; off >>= 1) ss += __shfl_xor_sync(0xffffffffu, ss, off);
    __shared__ float red[8];
    if ((t & 31) == 0) red[t >> 5] = ss;
    __syncthreads();
    if (t < 8) {
        float x = red[t];
#pragma unroll
        for (int off = 4; off; off >>= 1) x += __shfl_xor_sync(0xffu, x, off);
        if (t == 0) red[0] = x;
    }
    __syncthreads();
    float scale = rsqrtf(red[0] * (1.0f / (float)D) + 1e-6f);
#pragma unroll
    for (int i = 0; i < 4; i++) out[t + i * 256] = v[i] * scale * w[t + i * 256];
}

// ---------------- MMA helpers ----------------
#define LDSM4(r0, r1, r2, r3, addr)                                          \
    asm volatile("ldmatrix.sync.aligned.m8n8.x4.shared.b16 {%0,%1,%2,%3},[%4];" \
                 : "=r"(r0), "=r"(r1), "=r"(r2), "=r"(r3) : "r"(addr))
#define LDSM4T(r0, r1, r2, r3, addr)                                         \
    asm volatile("ldmatrix.sync.aligned.m8n8.x4.trans.shared.b16 {%0,%1,%2,%3},[%4];" \
                 : "=r"(r0), "=r"(r1), "=r"(r2), "=r"(r3) : "r"(addr))
#define CP_ASYNC16(saddr, gaddr)                                             \
    asm volatile("cp.async.cg.shared.global [%0],[%1],16;" :: "r"(saddr), "l"(gaddr))
#define CP_COMMIT() asm volatile("cp.async.commit_group;" ::: "memory")
#define CP_WAIT1()  asm volatile("cp.async.wait_group 1;" ::: "memory")

__device__ __forceinline__ void mma16816(float* c, const unsigned* a, const unsigned* b) {
    asm volatile(
        "mma.sync.aligned.m16n8k16.row.col.f32.bf16.bf16.f32 "
        "{%0,%1,%2,%3},{%4,%5,%6,%7},{%8,%9},{%0,%1,%2,%3};"
        : "+f"(c[0]), "+f"(c[1]), "+f"(c[2]), "+f"(c[3])
        : "r"(a[0]), "r"(a[1]), "r"(a[2]), "r"(a[3]), "r"(b[0]), "r"(b[1]));
}

// ---------------- bf16x3 GEMM: cp.async 3-stage + register-double-buffered frags ----------------
#define GBM 128
#define GBN 128
#define GBK 32
#define NSTAGE 3
#define A_BUF_BYTES 10240
#define B_BUF_BYTES 8704
#define A_STAGE_BYTES 20480
#define STAGE_BYTES 37888
#define SMEM_BYTES (NSTAGE * STAGE_BYTES)

extern __shared__ char gsmem[];

template <int MODE>
__global__ __launch_bounds__(256) void gemm_bf16x3_kernel(
    const bf16* __restrict__ Ah, const bf16* __restrict__ Al,
    const bf16* __restrict__ Bh, const bf16* __restrict__ Bl,
    const float* __restrict__ RES, float* __restrict__ C,
    bf16* __restrict__ O1h, bf16* __restrict__ O1l,
    bf16* __restrict__ O2h, bf16* __restrict__ O2l,
    bf16* __restrict__ O3h, bf16* __restrict__ O3l,
    const float* __restrict__ ct, const float* __restrict__ st,
    int M, int N, int K) {
    const int tid  = threadIdx.x;
    const int bm   = blockIdx.y * GBM;
    const int bn   = blockIdx.x * GBN;
    const int warp = tid >> 5;
    const int lane = tid & 31;
    const int wm   = (warp >> 2) * 64;
    const int wn   = (warp & 3) * 32;
    const int grp  = lane >> 3;
    const int rin  = lane & 7;

    const uint32_t sBase = (uint32_t)__cvta_generic_to_shared(gsmem);
    const uint32_t laneA = (uint32_t)((((grp & 1) << 3) + rin) * 80 + ((grp >> 1) << 4));
    const uint32_t laneB = (uint32_t)((((grp & 1) << 3) + rin) * 272 + (((grp >> 1) << 3) + wn) * 2);

    float acc[4][4][4];
#pragma unroll
    for (int mi = 0; mi < 4; mi++)
#pragma unroll
        for (int ni = 0; ni < 4; ni++)
#pragma unroll
            for (int j = 0; j < 4; j++) acc[mi][ni][j] = 0.f;

    const int KT = K / GBK;

    auto issue = [&](int kt, int stage) {
        const uint32_t stOff = sBase + stage * STAGE_BYTES;
        const int kOff = kt * GBK;
#pragma unroll
        for (int i = 0; i < 4; i++) {
            int c = tid + 256 * i;
            int buf = c >> 9, rem = c & 511;
            int m = rem >> 2, kq = rem & 3;
            const bf16* g = (buf ? Al : Ah) + (size_t)(bm + m) * K + kOff + kq * 8;
            uint32_t sa = stOff + buf * A_BUF_BYTES + m * 80 + kq * 16;
            CP_ASYNC16(sa, g);
        }
#pragma unroll
        for (int i = 0; i < 4; i++) {
            int c = tid + 256 * i;
            int buf = c >> 9, rem = c & 511;
            int kk = rem >> 4, nq = rem & 15;
            const bf16* g = (buf ? Bl : Bh) + (size_t)(kOff + kk) * N + bn + nq * 8;
            uint32_t sa = stOff + A_STAGE_BYTES + buf * B_BUF_BYTES + kk * 272 + nq * 16;
            CP_ASYNC16(sa, g);
        }
    };

    auto load_frags = [&](unsigned (&a)[2][4][4], unsigned (&b)[2][4][2],
                          uint32_t stOff, int ks) {
#pragma unroll
        for (int buf = 0; buf < 2; buf++) {
            uint32_t aS = stOff + buf * A_BUF_BYTES + laneA + ks * 32;
#pragma unroll
            for (int mt = 0; mt < 4; mt++) {
                uint32_t addr = aS + (wm + mt * 16) * 80;
                LDSM4(a[buf][mt][0], a[buf][mt][1], a[buf][mt][2], a[buf][mt][3], addr);
            }
            uint32_t bS = stOff + A_STAGE_BYTES + buf * B_BUF_BYTES + laneB + ks * 4352;
#pragma unroll
            for (int nj = 0; nj < 2; nj++) {
                uint32_t addr = bS + nj * 32;
                LDSM4T(b[buf][2 * nj][0], b[buf][2 * nj][1],
                       b[buf][2 * nj + 1][0], b[buf][2 * nj + 1][1], addr);
            }
        }
    };

    auto do_mma = [&](unsigned (&a)[2][4][4], unsigned (&b)[2][4][2]) {
#pragma unroll
        for (int mt = 0; mt < 4; mt++)
#pragma unroll
            for (int nt = 0; nt < 4; nt++)
                mma16816(acc[mt][nt], a[0][mt], b[0][nt]);
#pragma unroll
        for (int mt = 0; mt < 4; mt++)
#pragma unroll
            for (int nt = 0; nt < 4; nt++)
                mma16816(acc[mt][nt], a[0][mt], b[1][nt]);
#pragma unroll
        for (int mt = 0; mt < 4; mt++)
#pragma unroll
            for (int nt = 0; nt < 4; nt++)
                mma16816(acc[mt][nt], a[1][mt], b[0][nt]);
    };

    unsigned aX[2][4][4], bX[2][4][2];
    unsigned aY[2][4][4], bY[2][4][2];

    issue(0, 0); CP_COMMIT();
    issue(1, 1); CP_COMMIT();
    CP_WAIT1();
    __syncthreads();
    load_frags(aX, bX, sBase, 0);

    for (int kt = 0; kt < KT; kt++) {
        const uint32_t stOff = sBase + (kt % NSTAGE) * STAGE_BYTES;
        load_frags(aY, bY, stOff, 1);
        do_mma(aX, bX);
        if (kt + 2 < KT) issue(kt + 2, (kt + 2) % NSTAGE);
        CP_COMMIT();
        CP_WAIT1();
        __syncthreads();
        if (kt + 1 < KT)
            load_frags(aX, bX, sBase + ((kt + 1) % NSTAGE) * STAGE_BYTES, 0);
        do_mma(aY, bY);
    }

    // ---- fused epilogue ----
    const int r0 = bm + wm + (lane >> 2);
    const int c0 = bn + wn + (lane & 3) * 2;
#pragma unroll
    for (int mt = 0; mt < 4; mt++)
#pragma unroll
        for (int nt = 0; nt < 4; nt++) {
            const int col = c0 + nt * 8;
#pragma unroll
            for (int rp = 0; rp < 2; rp++) {
                const int row = r0 + mt * 16 + rp * 8;
                float2 v = make_float2(acc[mt][nt][2 * rp], acc[mt][nt][2 * rp + 1]);
                if (MODE == 0) {
                    if (RES) {
                        float2 a0 = *(const float2*)(RES + (size_t)row * N + col);
                        v.x += a0.x; v.y += a0.y;
                    }
                    *(float2*)(C + (size_t)row * N + col) = v;
                } else if (MODE == 1) {
                    const int seg = col >> 10;
                    const int d = col & 1023;
                    if (seg < 2) {
                        const int i = (d & 63) >> 1;
                        float c = ct[row * 32 + i];
                        float s = st[row * 32 + i];
                        float a0 = v.x * c - v.y * s;
                        float b0 = v.x * s + v.y * c;
                        v.x = a0; v.y = b0;
                    }
                    unsigned hp, lp;
                    split2pack(v.x, v.y, hp, lp);
                    bf16* oh = (seg == 0) ? O1h : (seg == 1) ? O2h : O3h;
                    bf16* ol = (seg == 0) ? O1l : (seg == 1) ? O2l : O3l;
                    *(unsigned*)(oh + (size_t)row * D + d) = hp;
                    *(unsigned*)(ol + (size_t)row * D + d) = lp;
                } else {
                    const int j = col >> 1;
                    float z = v.x;
                    float sig = 1.0f / (1.0f + __expf(-z));
                    float r = z * sig * v.y;
                    bf16 h, l; split1(r, h, l);
                    O1h[(size_t)row * HFF + j] = h;
                    O1l[(size_t)row * HFF + j] = l;
                }
            }
        }
}

// ---------------- Tensor-core flash attention: 256 thr, 128-query tiles ----------------
#define AP 72   // smem row pitch in halfs (144B)

__global__ __launch_bounds__(256) void attn_mma_kernel(
    const bf16* __restrict__ Qh, const bf16* __restrict__ Ql,
    const bf16* __restrict__ Kh, const bf16* __restrict__ Kl,
    const bf16* __restrict__ Vh, const bf16* __restrict__ Vl,
    bf16* __restrict__ Oh, bf16* __restrict__ Ol) {
    __shared__ __align__(16) bf16 sK[2][64 * AP];
    __shared__ __align__(16) bf16 sV[2][64 * AP];

    const int qt   = gridDim.x - 1 - blockIdx.x;   // longest-first
    const int head = blockIdx.y;
    const int tid  = threadIdx.x;
    const int warp = tid >> 5;
    const int lane = tid & 31;
    const int grp  = lane >> 3;
    const int rin  = lane & 7;
    const int wq   = warp * 16;                    // warp's first q-row (0..112)

    // ---- stage Q (128 rows hi/lo): hi rows0-63->sK[0], hi64-127->sK[1],
    //      lo rows0-63->sV[0], lo64-127->sV[1] ----
    {
#pragma unroll
        for (int c = tid; c < 2048; c += 256) {
            int buf = c >> 10, rem = c & 1023;      // buf 0=hi 1=lo
            int row = rem >> 3, col8 = rem & 7;
            bf16* dst = buf ? (row < 64 ? sV[0] : sV[1]) : (row < 64 ? sK[0] : sK[1]);
            *(uint4*)&dst[(row & 63) * AP + col8 * 8] =
                *(const uint4*)((buf ? Ql : Qh) + (size_t)(qt * 128 + row) * D + head * HD + col8 * 8);
        }
    }
    __syncthreads();

    unsigned aQ[2][4][4];
    {
        const int hb = wq >> 6;                     // which 64-row half
        const int rowin = wq & 63;
        uint32_t bH = (uint32_t)__cvta_generic_to_shared(&sK[hb][0]);
        uint32_t bL = (uint32_t)__cvta_generic_to_shared(&sV[hb][0]);
        uint32_t laneOff = (uint32_t)(((rowin + ((grp & 1) << 3) + rin) * AP + ((grp >> 1) << 3)) << 1);
#pragma unroll
        for (int kc = 0; kc < 4; kc++) {
            LDSM4(aQ[0][kc][0], aQ[0][kc][1], aQ[0][kc][2], aQ[0][kc][3], bH + laneOff + kc * 32);
            LDSM4(aQ[1][kc][0], aQ[1][kc][1], aQ[1][kc][2], aQ[1][kc][3], bL + laneOff + kc * 32);
        }
    }

    float o[8][4];
#pragma unroll
    for (int nt = 0; nt < 8; nt++)
#pragma unroll
        for (int j = 0; j < 4; j++) o[nt][j] = 0.f;
    float m0 = -1e30f, m1 = -1e30f, l0 = 0.f, l1 = 0.f;
    const float scale = 0.125f;

    const uint32_t sK0 = (uint32_t)__cvta_generic_to_shared(&sK[0][0]);
    const uint32_t sK1 = (uint32_t)__cvta_generic_to_shared(&sK[1][0]);
    const uint32_t sV0 = (uint32_t)__cvta_generic_to_shared(&sV[0][0]);
    const uint32_t sV1 = (uint32_t)__cvta_generic_to_shared(&sV[1][0]);

    const int r0g = qt * 128 + wq + (lane >> 2);
    const int r1g = r0g + 8;
    const int warpMaxRow = qt * 128 + wq + 15;
    const int ktMax = 2 * qt + 1;                   // inclusive

    for (int kt = 0; kt <= ktMax; kt++) {
        __syncthreads();
        {
            const bf16* src[4] = {Kh, Kl, Vh, Vl};
            bf16* dst[4] = {sK[0], sK[1], sV[0], sV[1]};
#pragma unroll
            for (int c = tid; c < 2048; c += 256) {
                int which = c >> 9, rem = c & 511;
                int row = rem >> 3, col8 = rem & 7;
                *(uint4*)&dst[which][row * AP + col8 * 8] =
                    *(const uint4*)(src[which] + (size_t)(kt * 64 + row) * D + head * HD + col8 * 8);
            }
        }
        __syncthreads();

        if (kt * 64 > warpMaxRow) continue;         // fully masked for this warp

        float s[8][4];
#pragma unroll
        for (int nt = 0; nt < 8; nt++)
#pragma unroll
            for (int j = 0; j < 4; j++) s[nt][j] = 0.f;

#pragma unroll
        for (int kc = 0; kc < 4; kc++) {
            unsigned bh[8][2], bl[8][2];
#pragma unroll
            for (int np = 0; np < 4; np++) {
                uint32_t off = (uint32_t)(((np * 16 + ((grp >> 1) << 3) + rin) * AP
                                           + kc * 16 + ((grp & 1) << 3)) << 1);
                LDSM4(bh[2 * np][0], bh[2 * np][1], bh[2 * np + 1][0], bh[2 * np + 1][1], sK0 + off);
                LDSM4(bl[2 * np][0], bl[2 * np][1], bl[2 * np + 1][0], bl[2 * np + 1][1], sK1 + off);
            }
#pragma unroll
            for (int nt = 0; nt < 8; nt++) mma16816(s[nt], aQ[0][kc], bh[nt]);
#pragma unroll
            for (int nt = 0; nt < 8; nt++) mma16816(s[nt], aQ[0][kc], bl[nt]);
#pragma unroll
            for (int nt = 0; nt < 8; nt++) mma16816(s[nt], aQ[1][kc], bh[nt]);
        }

        const bool needMask = (kt * 64 + 63 > r0g - (lane >> 2));  // tile can clip this warp
#pragma unroll
        for (int nt = 0; nt < 8; nt++) {
            int c0g = kt * 64 + nt * 8 + (lane & 3) * 2;
            s[nt][0] *= scale; s[nt][1] *= scale;
            s[nt][2] *= scale; s[nt][3] *= scale;
            if (needMask) {
                if (c0g     > r0g) s[nt][0] = -1e30f;
                if (c0g + 1 > r0g) s[nt][1] = -1e30f;
                if (c0g     > r1g) s[nt][2] = -1e30f;
                if (c0g + 1 > r1g) s[nt][3] = -1e30f;
            }
        }

        float mx0 = -1e30f, mx1 = -1e30f;
#pragma unroll
        for (int nt = 0; nt < 8; nt++) {
            mx0 = fmaxf(mx0, fmaxf(s[nt][0], s[nt][1]));
            mx1 = fmaxf(mx1, fmaxf(s[nt][2], s[nt][3]));
        }
        mx0 = fmaxf(mx0, __shfl_xor_sync(0xffffffffu, mx0, 1));
        mx0 = fmaxf(mx0, __shfl_xor_sync(0xffffffffu, mx0, 2));
        mx1 = fmaxf(mx1, __shfl_xor_sync(0xffffffffu, mx1, 1));
        mx1 = fmaxf(mx1, __shfl_xor_sync(0xffffffffu, mx1, 2));
        float mn0 = fmaxf(m0, mx0), mn1 = fmaxf(m1, mx1);
        float cr0 = __expf(m0 - mn0), cr1 = __expf(m1 - mn1);
        m0 = mn0; m1 = mn1;
        float rs0 = 0.f, rs1 = 0.f;
#pragma unroll
        for (int nt = 0; nt < 8; nt++) {
            s[nt][0] = __expf(s[nt][0] - mn0); rs0 += s[nt][0];
            s[nt][1] = __expf(s[nt][1] - mn0); rs0 += s[nt][1];
            s[nt][2] = __expf(s[nt][2] - mn1); rs1 += s[nt][2];
            s[nt][3] = __expf(s[nt][3] - mn1); rs1 += s[nt][3];
        }
        l0 = l0 * cr0 + rs0;
        l1 = l1 * cr1 + rs1;
#pragma unroll
        for (int nt = 0; nt < 8; nt++) {
            o[nt][0] *= cr0; o[nt][1] *= cr0;
            o[nt][2] *= cr1; o[nt][3] *= cr1;
        }

#pragma unroll
        for (int kc = 0; kc < 4; kc++) {
            int t0 = 2 * kc, t1 = 2 * kc + 1;
            unsigned ah[4], al[4];
            split2pack(s[t0][0], s[t0][1], ah[0], al[0]);
            split2pack(s[t0][2], s[t0][3], ah[1], al[1]);
            split2pack(s[t1][0], s[t1][1], ah[2], al[2]);
            split2pack(s[t1][2], s[t1][3], ah[3], al[3]);

            unsigned bvh[8][2], bvl[8][2];
#pragma unroll
            for (int np = 0; np < 4; np++) {
                uint32_t off = (uint32_t)(((kc * 16 + ((grp & 1) << 3) + rin) * AP
                                           + np * 16 + ((grp >> 1) << 3)) << 1);
                LDSM4T(bvh[2 * np][0], bvh[2 * np][1], bvh[2 * np + 1][0], bvh[2 * np + 1][1], sV0 + off);
                LDSM4T(bvl[2 * np][0], bvl[2 * np][1], bvl[2 * np + 1][0], bvl[2 * np + 1][1], sV1 + off);
            }
#pragma unroll
            for (int nt = 0; nt < 8; nt++) mma16816(o[nt], ah, bvh[nt]);
#pragma unroll
            for (int nt = 0; nt < 8; nt++) mma16816(o[nt], ah, bvl[nt]);
#pragma unroll
            for (int nt = 0; nt < 8; nt++) mma16816(o[nt], al, bvh[nt]);
        }
    }

    l0 += __shfl_xor_sync(0xffffffffu, l0, 1);
    l0 += __shfl_xor_sync(0xffffffffu, l0, 2);
    l1 += __shfl_xor_sync(0xffffffffu, l1, 1);
    l1 += __shfl_xor_sync(0xffffffffu, l1, 2);
    float inv0 = 1.f / l0, inv1 = 1.f / l1;
#pragma unroll
    for (int nt = 0; nt < 8; nt++) {
        int col = head * HD + nt * 8 + (lane & 3) * 2;
        unsigned hp, lp;
        split2pack(o[nt][0] * inv0, o[nt][1] * inv0, hp, lp);
        *(unsigned*)(Oh + (size_t)r0g * D + col) = hp;
        *(unsigned*)(Ol + (size_t)r0g * D + col) = lp;
        split2pack(o[nt][2] * inv1, o[nt][3] * inv1, hp, lp);
        *(unsigned*)(Oh + (size_t)r1g * D + col) = hp;
        *(unsigned*)(Ol + (size_t)r1g * D + col) = lp;
    }
}

// ---------------- Logits ----------------
__global__ void logits_kernel(const float* __restrict__ xf,
                              const float* __restrict__ Wout,
                              float* __restrict__ out) {
    __shared__ float xs[D];
    for (int i = threadIdx.x; i < D; i += 256) xs[i] = xf[i];
    __syncthreads();
    int v = blockIdx.x * 256 + threadIdx.x;
    float acc = 0.f;
#pragma unroll 8
    for (int d = 0; d < D; d++) acc += xs[d] * Wout[(size_t)d * NV + v];
    out[v] = acc;
}

// ---------------- Host launch ----------------
extern "C" void kernel_launch(void* const* d_in, const int* in_sizes, int n_in,
                              void* d_out, int out_size) {
    int bi = 1;
    if (n_in >= 2 && in_sizes[1] == 1) bi = 2;
    const int*   tokens  = (const int*)d_in[0];
    const float* tok_emb = (const float*)d_in[bi + 0];
    const float* Wq      = (const float*)d_in[bi + 1];
    const float* Wk      = (const float*)d_in[bi + 2];
    const float* Wv      = (const float*)d_in[bi + 3];
    const float* Wo      = (const float*)d_in[bi + 4];
    const float* W1      = (const float*)d_in[bi + 5];
    const float* W2      = (const float*)d_in[bi + 6];
    const float* W3      = (const float*)d_in[bi + 7];
    const float* anw     = (const float*)d_in[bi + 8];
    const float* fnw     = (const float*)d_in[bi + 9];
    const float* finw    = (const float*)d_in[bi + 10];
    const float* Wout    = (const float*)d_in[bi + 11];
    float* out = (float*)d_out;

    float *h_, *cos_, *sin_, *xf_;
    bf16 *xh_, *xl_, *oh_, *ol_, *gh_, *gl_;
    bf16 *qh_, *ql_, *kh_, *kl_, *vh_, *vl_;
    bf16 *wqkvh_, *wqkvl_, *w13h_, *w13l_, *woh_, *wol_, *w2h_, *w2l_;

    cudaGetSymbolAddress((void**)&h_,  g_h);
    cudaGetSymbolAddress((void**)&cos_, g_cos);
    cudaGetSymbolAddress((void**)&sin_, g_sin);
    cudaGetSymbolAddress((void**)&xf_, g_xf);
    cudaGetSymbolAddress((void**)&xh_, g_xh);
    cudaGetSymbolAddress((void**)&xl_, g_xl);
    cudaGetSymbolAddress((void**)&oh_, g_oh);
    cudaGetSymbolAddress((void**)&ol_, g_ol);
    cudaGetSymbolAddress((void**)&gh_, g_gh);
    cudaGetSymbolAddress((void**)&gl_, g_gl);
    cudaGetSymbolAddress((void**)&qh_, g_qh); cudaGetSymbolAddress((void**)&ql_, g_ql);
    cudaGetSymbolAddress((void**)&kh_, g_kh); cudaGetSymbolAddress((void**)&kl_, g_kl);
    cudaGetSymbolAddress((void**)&vh_, g_vh); cudaGetSymbolAddress((void**)&vl_, g_vl);
    cudaGetSymbolAddress((void**)&wqkvh_, g_wqkvh); cudaGetSymbolAddress((void**)&wqkvl_, g_wqkvl);
    cudaGetSymbolAddress((void**)&w13h_, g_w13h); cudaGetSymbolAddress((void**)&w13l_, g_w13l);
    cudaGetSymbolAddress((void**)&woh_, g_woh); cudaGetSymbolAddress((void**)&wol_, g_wol);
    cudaGetSymbolAddress((void**)&w2h_, g_w2h); cudaGetSymbolAddress((void**)&w2l_, g_w2l);

    static int smem_set = 0;
    if (!smem_set) {
        cudaFuncSetAttribute(gemm_bf16x3_kernel<0>,
                             cudaFuncAttributeMaxDynamicSharedMemorySize, SMEM_BYTES);
        cudaFuncSetAttribute(gemm_bf16x3_kernel<1>,
                             cudaFuncAttributeMaxDynamicSharedMemorySize, SMEM_BYTES);
        cudaFuncSetAttribute(gemm_bf16x3_kernel<2>,
                             cudaFuncAttributeMaxDynamicSharedMemorySize, SMEM_BYTES);
        smem_set = 1;
    }

    {
        dim3 grid((unsigned)(PACK_TOTAL / 256), 1, NL);
        pack_all_kernel<<<grid, 256>>>(Wq, Wk, Wv, W1, W3, Wo, W2,
                                       wqkvh_, wqkvl_, w13h_, w13l_,
                                       woh_, wol_, w2h_, w2l_);
    }

    rope_table_kernel<<<(S * 32 + 255) / 256, 256>>>(cos_, sin_);
    embed_kernel<<<(S * D) / 256, 256>>>(tokens, tok_emb, h_);

    const dim3 gQKV(3 * D / GBN, S / GBM);   // (24, 16)
    const dim3 gDD(D / GBN, S / GBM);        // (8, 16)
    const dim3 gW13(2 * HFF / GBN, S / GBM); // (44, 16)

    for (int l = 0; l < NL; l++) {
        size_t offQKV = (size_t)l * 3 * D * D;
        size_t offDD  = (size_t)l * D * D;
        size_t off13  = (size_t)l * 2 * D * HFF;
        size_t offFD  = (size_t)l * HFF * D;

        rmsnorm_split_kernel<<<S, 256>>>(h_, anw + (size_t)l * D, xh_, xl_);

        gemm_bf16x3_kernel<1><<<gQKV, 256, SMEM_BYTES>>>(
            xh_, xl_, wqkvh_ + offQKV, wqkvl_ + offQKV, nullptr, nullptr,
            qh_, ql_, kh_, kl_, vh_, vl_, cos_, sin_, S, 3 * D, D);

        attn_mma_kernel<<<dim3(S / 128, NH), 256>>>(qh_, ql_, kh_, kl_, vh_, vl_, oh_, ol_);

        gemm_bf16x3_kernel<0><<<gDD, 256, SMEM_BYTES>>>(
            oh_, ol_, woh_ + offDD, wol_ + offDD, h_, h_,
            nullptr, nullptr, nullptr, nullptr, nullptr, nullptr, nullptr, nullptr, S, D, D);

        rmsnorm_split_kernel<<<S, 256>>>(h_, fnw + (size_t)l * D, xh_, xl_);

        gemm_bf16x3_kernel<2><<<gW13, 256, SMEM_BYTES>>>(
            xh_, xl_, w13h_ + off13, w13l_ + off13, nullptr, nullptr,
            gh_, gl_, nullptr, nullptr, nullptr, nullptr, nullptr, nullptr, S, 2 * HFF, D);

        gemm_bf16x3_kernel<0><<<gDD, 256, SMEM_BYTES>>>(
            gh_, gl_, w2h_ + offFD, w2l_ + offFD, h_, h_,
            nullptr, nullptr, nullptr, nullptr, nullptr, nullptr, nullptr, nullptr, S, D, HFF);
    }

    rmsnorm_kernel<<<1, 256>>>(h_ + (size_t)(S - 1) * D, finw, xf_);
    logits_kernel<<<NV / 256, 256>>>(xf_, Wout, out);
}

// round 11
// speedup vs baseline: 1.0715x; 1.0715x over previous
#include <cuda_runtime.h>
#include <cuda_bf16.h>
#include <math.h>
#include <stdint.h>

// ---------------- Problem constants ----------------
#define S    2048
#define D    1024
#define NH   16
#define HD   64
#define HFF  2816
#define NV   32000
#define NL   4

typedef __nv_bfloat16 bf16;

// ---------------- Device scratch ----------------
__device__ float g_h[S * D];
__device__ float g_cos[S * 32];
__device__ float g_sin[S * 32];
__device__ float g_xf[D];

__device__ __align__(16) bf16 g_xh[S * D],  g_xl[S * D];
__device__ __align__(16) bf16 g_oh[S * D],  g_ol[S * D];
__device__ __align__(16) bf16 g_gh[S * HFF], g_gl[S * HFF];
__device__ __align__(16) bf16 g_qh[S * D], g_ql[S * D];
__device__ __align__(16) bf16 g_kh[S * D], g_kl[S * D];
__device__ __align__(16) bf16 g_vh[S * D], g_vl[S * D];

__device__ __align__(16) bf16 g_wqkvh[NL * D * 3 * D], g_wqkvl[NL * D * 3 * D];
__device__ __align__(16) bf16 g_w13h[NL * D * 2 * HFF], g_w13l[NL * D * 2 * HFF];
__device__ __align__(16) bf16 g_woh[NL * D * D], g_wol[NL * D * D];
__device__ __align__(16) bf16 g_w2h[NL * HFF * D], g_w2l[NL * HFF * D];

// ---------------- small helpers ----------------
__device__ __forceinline__ void split1(float v, bf16& h, bf16& l) {
    h = __float2bfloat16(v);
    l = __float2bfloat16(v - __bfloat162float(h));
}
__device__ __forceinline__ void split2pack(float x, float y, unsigned& hp, unsigned& lp) {
    bf16 hx = __float2bfloat16(x), hy = __float2bfloat16(y);
    float lx = x - __bfloat162float(hx), ly = y - __bfloat162float(hy);
    bf16 lxb = __float2bfloat16(lx), lyb = __float2bfloat16(ly);
    hp = (unsigned)(*(unsigned short*)&hx) | ((unsigned)(*(unsigned short*)&hy) << 16);
    lp = (unsigned)(*(unsigned short*)&lxb) | ((unsigned)(*(unsigned short*)&lyb) << 16);
}

// ---------------- ONE fused pack+split kernel for all weights ----------------
#define PDD (D * D / 2)
#define PDF (D * HFF / 2)
__global__ void pack_all_kernel(
    const float* __restrict__ Wq, const float* __restrict__ Wk, const float* __restrict__ Wv,
    const float* __restrict__ W1, const float* __restrict__ W3,
    const float* __restrict__ Wo, const float* __restrict__ W2,
    bf16* __restrict__ qkvh, bf16* __restrict__ qkvl,
    bf16* __restrict__ w13h, bf16* __restrict__ w13l,
    bf16* __restrict__ woh, bf16* __restrict__ wol,
    bf16* __restrict__ w2h, bf16* __restrict__ w2l) {
    const int l = blockIdx.z;
    long idx = (long)blockIdx.x * 256 + threadIdx.x;

    if (idx < 3L * PDD) {
        int seg = (int)(idx / PDD);
        int r = (int)(idx % PDD);
        const float* src = (seg == 0 ? Wq : seg == 1 ? Wk : Wv) + (size_t)l * D * D;
        int k = r / (D / 2), n = (r % (D / 2)) * 2;
        float2 v = *(const float2*)(src + (size_t)k * D + n);
        unsigned hp, lp; split2pack(v.x, v.y, hp, lp);
        size_t o = (size_t)l * 3 * D * D + (size_t)k * 3 * D + seg * D + n;
        *(unsigned*)(qkvh + o) = hp;
        *(unsigned*)(qkvl + o) = lp;
        return;
    }
    idx -= 3L * PDD;
    if (idx < 2L * PDF) {
        int seg = (int)(idx / PDF);
        int r = (int)(idx % PDF);
        const float* src = (seg == 0 ? W1 : W3) + (size_t)l * D * HFF;
        int k = r / (HFF / 2), n = (r % (HFF / 2)) * 2;
        float2 v = *(const float2*)(src + (size_t)k * HFF + n);
        bf16 h, lo;
        size_t o = (size_t)l * 2 * D * HFF + (size_t)k * 2 * HFF + seg + 2 * n;
        split1(v.x, h, lo); w13h[o] = h; w13l[o] = lo;
        split1(v.y, h, lo); w13h[o + 2] = h; w13l[o + 2] = lo;
        return;
    }
    idx -= 2L * PDF;
    if (idx < PDD) {
        const float* src = Wo + (size_t)l * D * D;
        int k = (int)(idx / (D / 2)), n = (int)(idx % (D / 2)) * 2;
        float2 v = *(const float2*)(src + (size_t)k * D + n);
        unsigned hp, lp; split2pack(v.x, v.y, hp, lp);
        size_t o = (size_t)l * D * D + (size_t)k * D + n;
        *(unsigned*)(woh + o) = hp;
        *(unsigned*)(wol + o) = lp;
        return;
    }
    idx -= PDD;
    {
        const float* src = W2 + (size_t)l * HFF * D;
        int k = (int)(idx / (D / 2)), n = (int)(idx % (D / 2)) * 2;
        float2 v = *(const float2*)(src + (size_t)k * D + n);
        unsigned hp, lp; split2pack(v.x, v.y, hp, lp);
        size_t o = (size_t)l * HFF * D + (size_t)k * D + n;
        *(unsigned*)(w2h + o) = hp;
        *(unsigned*)(w2l + o) = lp;
    }
}
#define PACK_TOTAL (4L * PDD + 3L * PDF)

// ---------------- RoPE table ----------------
__global__ void rope_table_kernel(float* ct, float* st) {
    int idx = blockIdx.x * 256 + threadIdx.x;
    if (idx >= S * 32) return;
    int pos = idx >> 5;
    int i = idx & 31;
    float inv = powf(10000.0f, -((float)(2 * i) / (float)HD));
    float ang = (float)pos * inv;
    float s, c;
    sincosf(ang, &s, &c);
    ct[idx] = c;
    st[idx] = s;
}

// ---------------- Embedding gather ----------------
__global__ void embed_kernel(const int* __restrict__ tokens,
                             const float* __restrict__ emb,
                             float* __restrict__ h) {
    int idx = blockIdx.x * 256 + threadIdx.x;
    int s = idx >> 10;
    int d = idx & 1023;
    h[idx] = emb[(size_t)tokens[s] * D + d];
}

// ---------------- RMSNorm -> split bf16 hi/lo ----------------
__global__ void rmsnorm_split_kernel(const float* __restrict__ in,
                                     const float* __restrict__ w,
                                     bf16* __restrict__ oh, bf16* __restrict__ ol) {
    const float* r = in + (size_t)blockIdx.x * D;
    bf16* ph = oh + (size_t)blockIdx.x * D;
    bf16* pl = ol + (size_t)blockIdx.x * D;
    int t = threadIdx.x;
    float v[4];
    float ss = 0.f;
#pragma unroll
    for (int i = 0; i < 4; i++) { v[i] = r[t + i * 256]; ss += v[i] * v[i]; }
#pragma unroll
    for (int off = 16; off; off >>= 1) ss += __shfl_xor_sync(0xffffffffu, ss, off);
    __shared__ float red[8];
    if ((t & 31) == 0) red[t >> 5] = ss;
    __syncthreads();
    if (t < 8) {
        float x = red[t];
#pragma unroll
        for (int off = 4; off; off >>= 1) x += __shfl_xor_sync(0xffu, x, off);
        if (t == 0) red[0] = x;
    }
    __syncthreads();
    float scale = rsqrtf(red[0] * (1.0f / (float)D) + 1e-6f);
#pragma unroll
    for (int i = 0; i < 4; i++) {
        float rv = v[i] * scale * w[t + i * 256];
        bf16 h, l; split1(rv, h, l);
        ph[t + i * 256] = h;
        pl[t + i * 256] = l;
    }
}

// ---------------- plain fp32 RMSNorm (final row) ----------------
__global__ void rmsnorm_kernel(const float* __restrict__ in,
                               const float* __restrict__ w,
                               float* __restrict__ out) {
    const float* r = in;
    int t = threadIdx.x;
    float v[4];
    float ss = 0.f;
#pragma unroll
    for (int i = 0; i < 4; i++) { v[i] = r[t + i * 256]; ss += v[i] * v[i]; }
#pragma unroll
    for (int off = 16; off; off >>= 1) ss += __shfl_xor_sync(0xffffffffu, ss, off);
    __shared__ float red[8];
    if ((t & 31) == 0) red[t >> 5] = ss;
    __syncthreads();
    if (t < 8) {
        float x = red[t];
#pragma unroll
        for (int off = 4; off; off >>= 1) x += __shfl_xor_sync(0xffu, x, off);
        if (t == 0) red[0] = x;
    }
    __syncthreads();
    float scale = rsqrtf(red[0] * (1.0f / (float)D) + 1e-6f);
#pragma unroll
    for (int i = 0; i < 4; i++) out[t + i * 256] = v[i] * scale * w[t + i * 256];
}

// ---------------- MMA helpers ----------------
#define LDSM4(r0, r1, r2, r3, addr)                                          \
    asm volatile("ldmatrix.sync.aligned.m8n8.x4.shared.b16 {%0,%1,%2,%3},[%4];" \
                 : "=r"(r0), "=r"(r1), "=r"(r2), "=r"(r3) : "r"(addr))
#define LDSM4T(r0, r1, r2, r3, addr)                                         \
    asm volatile("ldmatrix.sync.aligned.m8n8.x4.trans.shared.b16 {%0,%1,%2,%3},[%4];" \
                 : "=r"(r0), "=r"(r1), "=r"(r2), "=r"(r3) : "r"(addr))
#define CP_ASYNC16(saddr, gaddr)                                             \
    asm volatile("cp.async.cg.shared.global [%0],[%1],16;" :: "r"(saddr), "l"(gaddr))
#define CP_COMMIT() asm volatile("cp.async.commit_group;" ::: "memory")
#define CP_WAIT2()  asm volatile("cp.async.wait_group 2;" ::: "memory")

__device__ __forceinline__ void mma16816(float* c, const unsigned* a, const unsigned* b) {
    asm volatile(
        "mma.sync.aligned.m16n8k16.row.col.f32.bf16.bf16.f32 "
        "{%0,%1,%2,%3},{%4,%5,%6,%7},{%8,%9},{%0,%1,%2,%3};"
        : "+f"(c[0]), "+f"(c[1]), "+f"(c[2]), "+f"(c[3])
        : "r"(a[0]), "r"(a[1]), "r"(a[2]), "r"(a[3]), "r"(b[0]), "r"(b[1]));
}

// ---------------- bf16x3 GEMM: cp.async 4-stage + register-double-buffered frags ----------------
#define GBM 128
#define GBN 128
#define GBK 32
#define NSTAGE 4
#define A_BUF_BYTES 10240
#define B_BUF_BYTES 8704
#define A_STAGE_BYTES 20480
#define STAGE_BYTES 37888
#define SMEM_BYTES (NSTAGE * STAGE_BYTES)

extern __shared__ char gsmem[];

template <int MODE>
__global__ __launch_bounds__(256) void gemm_bf16x3_kernel(
    const bf16* __restrict__ Ah, const bf16* __restrict__ Al,
    const bf16* __restrict__ Bh, const bf16* __restrict__ Bl,
    const float* __restrict__ RES, float* __restrict__ C,
    bf16* __restrict__ O1h, bf16* __restrict__ O1l,
    bf16* __restrict__ O2h, bf16* __restrict__ O2l,
    bf16* __restrict__ O3h, bf16* __restrict__ O3l,
    const float* __restrict__ ct, const float* __restrict__ st,
    int M, int N, int K) {
    const int tid  = threadIdx.x;
    const int bm   = blockIdx.y * GBM;
    const int bn   = blockIdx.x * GBN;
    const int warp = tid >> 5;
    const int lane = tid & 31;
    const int wm   = (warp >> 2) * 64;
    const int wn   = (warp & 3) * 32;
    const int grp  = lane >> 3;
    const int rin  = lane & 7;

    const uint32_t sBase = (uint32_t)__cvta_generic_to_shared(gsmem);
    const uint32_t laneA = (uint32_t)((((grp & 1) << 3) + rin) * 80 + ((grp >> 1) << 4));
    const uint32_t laneB = (uint32_t)((((grp & 1) << 3) + rin) * 272 + (((grp >> 1) << 3) + wn) * 2);

    float acc[4][4][4];
#pragma unroll
    for (int mi = 0; mi < 4; mi++)
#pragma unroll
        for (int ni = 0; ni < 4; ni++)
#pragma unroll
            for (int j = 0; j < 4; j++) acc[mi][ni][j] = 0.f;

    const int KT = K / GBK;

    auto issue = [&](int kt, int stage) {
        const uint32_t stOff = sBase + stage * STAGE_BYTES;
        const int kOff = kt * GBK;
#pragma unroll
        for (int i = 0; i < 4; i++) {
            int c = tid + 256 * i;
            int buf = c >> 9, rem = c & 511;
            int m = rem >> 2, kq = rem & 3;
            const bf16* g = (buf ? Al : Ah) + (size_t)(bm + m) * K + kOff + kq * 8;
            uint32_t sa = stOff + buf * A_BUF_BYTES + m * 80 + kq * 16;
            CP_ASYNC16(sa, g);
        }
#pragma unroll
        for (int i = 0; i < 4; i++) {
            int c = tid + 256 * i;
            int buf = c >> 9, rem = c & 511;
            int kk = rem >> 4, nq = rem & 15;
            const bf16* g = (buf ? Bl : Bh) + (size_t)(kOff + kk) * N + bn + nq * 8;
            uint32_t sa = stOff + A_STAGE_BYTES + buf * B_BUF_BYTES + kk * 272 + nq * 16;
            CP_ASYNC16(sa, g);
        }
    };

    auto load_frags = [&](unsigned (&a)[2][4][4], unsigned (&b)[2][4][2],
                          uint32_t stOff, int ks) {
#pragma unroll
        for (int buf = 0; buf < 2; buf++) {
            uint32_t aS = stOff + buf * A_BUF_BYTES + laneA + ks * 32;
#pragma unroll
            for (int mt = 0; mt < 4; mt++) {
                uint32_t addr = aS + (wm + mt * 16) * 80;
                LDSM4(a[buf][mt][0], a[buf][mt][1], a[buf][mt][2], a[buf][mt][3], addr);
            }
            uint32_t bS = stOff + A_STAGE_BYTES + buf * B_BUF_BYTES + laneB + ks * 4352;
#pragma unroll
            for (int nj = 0; nj < 2; nj++) {
                uint32_t addr = bS + nj * 32;
                LDSM4T(b[buf][2 * nj][0], b[buf][2 * nj][1],
                       b[buf][2 * nj + 1][0], b[buf][2 * nj + 1][1], addr);
            }
        }
    };

    auto do_mma = [&](unsigned (&a)[2][4][4], unsigned (&b)[2][4][2]) {
#pragma unroll
        for (int mt = 0; mt < 4; mt++)
#pragma unroll
            for (int nt = 0; nt < 4; nt++)
                mma16816(acc[mt][nt], a[0][mt], b[0][nt]);
#pragma unroll
        for (int mt = 0; mt < 4; mt++)
#pragma unroll
            for (int nt = 0; nt < 4; nt++)
                mma16816(acc[mt][nt], a[0][mt], b[1][nt]);
#pragma unroll
        for (int mt = 0; mt < 4; mt++)
#pragma unroll
            for (int nt = 0; nt < 4; nt++)
                mma16816(acc[mt][nt], a[1][mt], b[0][nt]);
    };

    unsigned aX[2][4][4], bX[2][4][2];
    unsigned aY[2][4][4], bY[2][4][2];

    issue(0, 0); CP_COMMIT();
    issue(1, 1); CP_COMMIT();
    issue(2, 2); CP_COMMIT();
    CP_WAIT2();                 // stage 0 done
    __syncthreads();
    load_frags(aX, bX, sBase, 0);

    for (int kt = 0; kt < KT; kt++) {
        const uint32_t stOff = sBase + (kt % NSTAGE) * STAGE_BYTES;
        load_frags(aY, bY, stOff, 1);
        do_mma(aX, bX);
        if (kt + 3 < KT) issue(kt + 3, (kt + 3) % NSTAGE);
        CP_COMMIT();
        CP_WAIT2();                          // stage kt+1 complete
        __syncthreads();
        if (kt + 1 < KT)
            load_frags(aX, bX, sBase + ((kt + 1) % NSTAGE) * STAGE_BYTES, 0);
        do_mma(aY, bY);
    }

    // ---- fused epilogue ----
    const int r0 = bm + wm + (lane >> 2);
    const int c0 = bn + wn + (lane & 3) * 2;
#pragma unroll
    for (int mt = 0; mt < 4; mt++)
#pragma unroll
        for (int nt = 0; nt < 4; nt++) {
            const int col = c0 + nt * 8;
#pragma unroll
            for (int rp = 0; rp < 2; rp++) {
                const int row = r0 + mt * 16 + rp * 8;
                float2 v = make_float2(acc[mt][nt][2 * rp], acc[mt][nt][2 * rp + 1]);
                if (MODE == 0) {
                    if (RES) {
                        float2 a0 = *(const float2*)(RES + (size_t)row * N + col);
                        v.x += a0.x; v.y += a0.y;
                    }
                    *(float2*)(C + (size_t)row * N + col) = v;
                } else if (MODE == 1) {
                    const int seg = col >> 10;
                    const int d = col & 1023;
                    if (seg < 2) {
                        const int i = (d & 63) >> 1;
                        float c = ct[row * 32 + i];
                        float s = st[row * 32 + i];
                        float a0 = v.x * c - v.y * s;
                        float b0 = v.x * s + v.y * c;
                        v.x = a0; v.y = b0;
                    }
                    unsigned hp, lp;
                    split2pack(v.x, v.y, hp, lp);
                    bf16* oh = (seg == 0) ? O1h : (seg == 1) ? O2h : O3h;
                    bf16* ol = (seg == 0) ? O1l : (seg == 1) ? O2l : O3l;
                    *(unsigned*)(oh + (size_t)row * D + d) = hp;
                    *(unsigned*)(ol + (size_t)row * D + d) = lp;
                } else {
                    const int j = col >> 1;
                    float z = v.x;
                    float sig = 1.0f / (1.0f + __expf(-z));
                    float r = z * sig * v.y;
                    bf16 h, l; split1(r, h, l);
                    O1h[(size_t)row * HFF + j] = h;
                    O1l[(size_t)row * HFF + j] = l;
                }
            }
        }
}

// ---------------- Tensor-core flash attention (R8 version: 128 thr, 64-q tiles) ----------------
#define AP 72   // smem row pitch in halfs (144B)

__global__ __launch_bounds__(128) void attn_mma_kernel(
    const bf16* __restrict__ Qh, const bf16* __restrict__ Ql,
    const bf16* __restrict__ Kh, const bf16* __restrict__ Kl,
    const bf16* __restrict__ Vh, const bf16* __restrict__ Vl,
    bf16* __restrict__ Oh, bf16* __restrict__ Ol) {
    __shared__ __align__(16) bf16 sK[2][64 * AP];
    __shared__ __align__(16) bf16 sV[2][64 * AP];

    const int qt   = gridDim.x - 1 - blockIdx.x;   // longest-first
    const int head = blockIdx.y;
    const int tid  = threadIdx.x;
    const int warp = tid >> 5;
    const int lane = tid & 31;
    const int grp  = lane >> 3;
    const int rin  = lane & 7;
    const int wq   = warp * 16;

    {
        const bf16* qsrc[2] = {Qh, Ql};
#pragma unroll
        for (int c = tid; c < 1024; c += 128) {
            int buf = c >> 9, rem = c & 511;
            int row = rem >> 3, col8 = rem & 7;
            *(uint4*)&sK[buf][row * AP + col8 * 8] =
                *(const uint4*)(qsrc[buf] + (size_t)(qt * 64 + row) * D + head * HD + col8 * 8);
        }
    }
    __syncthreads();

    unsigned aQ[2][4][4];
    {
        uint32_t b0 = (uint32_t)__cvta_generic_to_shared(&sK[0][0]);
        uint32_t b1 = (uint32_t)__cvta_generic_to_shared(&sK[1][0]);
        uint32_t laneOff = (uint32_t)(((wq + ((grp & 1) << 3) + rin) * AP + ((grp >> 1) << 3)) << 1);
#pragma unroll
        for (int kc = 0; kc < 4; kc++) {
            LDSM4(aQ[0][kc][0], aQ[0][kc][1], aQ[0][kc][2], aQ[0][kc][3], b0 + laneOff + kc * 32);
            LDSM4(aQ[1][kc][0], aQ[1][kc][1], aQ[1][kc][2], aQ[1][kc][3], b1 + laneOff + kc * 32);
        }
    }

    float o[8][4];
#pragma unroll
    for (int nt = 0; nt < 8; nt++)
#pragma unroll
        for (int j = 0; j < 4; j++) o[nt][j] = 0.f;
    float m0 = -1e30f, m1 = -1e30f, l0 = 0.f, l1 = 0.f;
    const float scale = 0.125f;

    const uint32_t sK0 = (uint32_t)__cvta_generic_to_shared(&sK[0][0]);
    const uint32_t sK1 = (uint32_t)__cvta_generic_to_shared(&sK[1][0]);
    const uint32_t sV0 = (uint32_t)__cvta_generic_to_shared(&sV[0][0]);
    const uint32_t sV1 = (uint32_t)__cvta_generic_to_shared(&sV[1][0]);

    const int r0g = qt * 64 + wq + (lane >> 2);
    const int r1g = r0g + 8;

    for (int kt = 0; kt <= qt; kt++) {
        __syncthreads();
        {
            const bf16* src[4] = {Kh, Kl, Vh, Vl};
            bf16* dst[4] = {sK[0], sK[1], sV[0], sV[1]};
#pragma unroll
            for (int c = tid; c < 2048; c += 128) {
                int which = c >> 9, rem = c & 511;
                int row = rem >> 3, col8 = rem & 7;
                *(uint4*)&dst[which][row * AP + col8 * 8] =
                    *(const uint4*)(src[which] + (size_t)(kt * 64 + row) * D + head * HD + col8 * 8);
            }
        }
        __syncthreads();

        float s[8][4];
#pragma unroll
        for (int nt = 0; nt < 8; nt++)
#pragma unroll
            for (int j = 0; j < 4; j++) s[nt][j] = 0.f;

#pragma unroll
        for (int kc = 0; kc < 4; kc++) {
            unsigned bh[8][2], bl[8][2];
#pragma unroll
            for (int np = 0; np < 4; np++) {
                uint32_t off = (uint32_t)(((np * 16 + ((grp >> 1) << 3) + rin) * AP
                                           + kc * 16 + ((grp & 1) << 3)) << 1);
                LDSM4(bh[2 * np][0], bh[2 * np][1], bh[2 * np + 1][0], bh[2 * np + 1][1], sK0 + off);
                LDSM4(bl[2 * np][0], bl[2 * np][1], bl[2 * np + 1][0], bl[2 * np + 1][1], sK1 + off);
            }
#pragma unroll
            for (int nt = 0; nt < 8; nt++) mma16816(s[nt], aQ[0][kc], bh[nt]);
#pragma unroll
            for (int nt = 0; nt < 8; nt++) mma16816(s[nt], aQ[0][kc], bl[nt]);
#pragma unroll
            for (int nt = 0; nt < 8; nt++) mma16816(s[nt], aQ[1][kc], bh[nt]);
        }

        const bool diag = (kt == qt);
#pragma unroll
        for (int nt = 0; nt < 8; nt++) {
            int c0g = kt * 64 + nt * 8 + (lane & 3) * 2;
            s[nt][0] *= scale; s[nt][1] *= scale;
            s[nt][2] *= scale; s[nt][3] *= scale;
            if (diag) {
                if (c0g     > r0g) s[nt][0] = -1e30f;
                if (c0g + 1 > r0g) s[nt][1] = -1e30f;
                if (c0g     > r1g) s[nt][2] = -1e30f;
                if (c0g + 1 > r1g) s[nt][3] = -1e30f;
            }
        }

        float mx0 = -1e30f, mx1 = -1e30f;
#pragma unroll
        for (int nt = 0; nt < 8; nt++) {
            mx0 = fmaxf(mx0, fmaxf(s[nt][0], s[nt][1]));
            mx1 = fmaxf(mx1, fmaxf(s[nt][2], s[nt][3]));
        }
        mx0 = fmaxf(mx0, __shfl_xor_sync(0xffffffffu, mx0, 1));
        mx0 = fmaxf(mx0, __shfl_xor_sync(0xffffffffu, mx0, 2));
        mx1 = fmaxf(mx1, __shfl_xor_sync(0xffffffffu, mx1, 1));
        mx1 = fmaxf(mx1, __shfl_xor_sync(0xffffffffu, mx1, 2));
        float mn0 = fmaxf(m0, mx0), mn1 = fmaxf(m1, mx1);
        float cr0 = __expf(m0 - mn0), cr1 = __expf(m1 - mn1);
        m0 = mn0; m1 = mn1;
        float rs0 = 0.f, rs1 = 0.f;
#pragma unroll
        for (int nt = 0; nt < 8; nt++) {
            s[nt][0] = __expf(s[nt][0] - mn0); rs0 += s[nt][0];
            s[nt][1] = __expf(s[nt][1] - mn0); rs0 += s[nt][1];
            s[nt][2] = __expf(s[nt][2] - mn1); rs1 += s[nt][2];
            s[nt][3] = __expf(s[nt][3] - mn1); rs1 += s[nt][3];
        }
        l0 = l0 * cr0 + rs0;
        l1 = l1 * cr1 + rs1;
#pragma unroll
        for (int nt = 0; nt < 8; nt++) {
            o[nt][0] *= cr0; o[nt][1] *= cr0;
            o[nt][2] *= cr1; o[nt][3] *= cr1;
        }

#pragma unroll
        for (int kc = 0; kc < 4; kc++) {
            int t0 = 2 * kc, t1 = 2 * kc + 1;
            unsigned ah[4], al[4];
            split2pack(s[t0][0], s[t0][1], ah[0], al[0]);
            split2pack(s[t0][2], s[t0][3], ah[1], al[1]);
            split2pack(s[t1][0], s[t1][1], ah[2], al[2]);
            split2pack(s[t1][2], s[t1][3], ah[3], al[3]);

            unsigned bvh[8][2], bvl[8][2];
#pragma unroll
            for (int np = 0; np < 4; np++) {
                uint32_t off = (uint32_t)(((kc * 16 + ((grp & 1) << 3) + rin) * AP
                                           + np * 16 + ((grp >> 1) << 3)) << 1);
                LDSM4T(bvh[2 * np][0], bvh[2 * np][1], bvh[2 * np + 1][0], bvh[2 * np + 1][1], sV0 + off);
                LDSM4T(bvl[2 * np][0], bvl[2 * np][1], bvl[2 * np + 1][0], bvl[2 * np + 1][1], sV1 + off);
            }
#pragma unroll
            for (int nt = 0; nt < 8; nt++) mma16816(o[nt], ah, bvh[nt]);
#pragma unroll
            for (int nt = 0; nt < 8; nt++) mma16816(o[nt], ah, bvl[nt]);
#pragma unroll
            for (int nt = 0; nt < 8; nt++) mma16816(o[nt], al, bvh[nt]);
        }
    }

    l0 += __shfl_xor_sync(0xffffffffu, l0, 1);
    l0 += __shfl_xor_sync(0xffffffffu, l0, 2);
    l1 += __shfl_xor_sync(0xffffffffu, l1, 1);
    l1 += __shfl_xor_sync(0xffffffffu, l1, 2);
    float inv0 = 1.f / l0, inv1 = 1.f / l1;
#pragma unroll
    for (int nt = 0; nt < 8; nt++) {
        int col = head * HD + nt * 8 + (lane & 3) * 2;
        unsigned hp, lp;
        split2pack(o[nt][0] * inv0, o[nt][1] * inv0, hp, lp);
        *(unsigned*)(Oh + (size_t)r0g * D + col) = hp;
        *(unsigned*)(Ol + (size_t)r0g * D + col) = lp;
        split2pack(o[nt][2] * inv1, o[nt][3] * inv1, hp, lp);
        *(unsigned*)(Oh + (size_t)r1g * D + col) = hp;
        *(unsigned*)(Ol + (size_t)r1g * D + col) = lp;
    }
}

// ---------------- Logits ----------------
__global__ void logits_kernel(const float* __restrict__ xf,
                              const float* __restrict__ Wout,
                              float* __restrict__ out) {
    __shared__ float xs[D];
    for (int i = threadIdx.x; i < D; i += 256) xs[i] = xf[i];
    __syncthreads();
    int v = blockIdx.x * 256 + threadIdx.x;
    float acc = 0.f;
#pragma unroll 8
    for (int d = 0; d < D; d++) acc += xs[d] * Wout[(size_t)d * NV + v];
    out[v] = acc;
}

// ---------------- Host launch ----------------
extern "C" void kernel_launch(void* const* d_in, const int* in_sizes, int n_in,
                              void* d_out, int out_size) {
    int bi = 1;
    if (n_in >= 2 && in_sizes[1] == 1) bi = 2;
    const int*   tokens  = (const int*)d_in[0];
    const float* tok_emb = (const float*)d_in[bi + 0];
    const float* Wq      = (const float*)d_in[bi + 1];
    const float* Wk      = (const float*)d_in[bi + 2];
    const float* Wv      = (const float*)d_in[bi + 3];
    const float* Wo      = (const float*)d_in[bi + 4];
    const float* W1      = (const float*)d_in[bi + 5];
    const float* W2      = (const float*)d_in[bi + 6];
    const float* W3      = (const float*)d_in[bi + 7];
    const float* anw     = (const float*)d_in[bi + 8];
    const float* fnw     = (const float*)d_in[bi + 9];
    const float* finw    = (const float*)d_in[bi + 10];
    const float* Wout    = (const float*)d_in[bi + 11];
    float* out = (float*)d_out;

    float *h_, *cos_, *sin_, *xf_;
    bf16 *xh_, *xl_, *oh_, *ol_, *gh_, *gl_;
    bf16 *qh_, *ql_, *kh_, *kl_, *vh_, *vl_;
    bf16 *wqkvh_, *wqkvl_, *w13h_, *w13l_, *woh_, *wol_, *w2h_, *w2l_;

    cudaGetSymbolAddress((void**)&h_,  g_h);
    cudaGetSymbolAddress((void**)&cos_, g_cos);
    cudaGetSymbolAddress((void**)&sin_, g_sin);
    cudaGetSymbolAddress((void**)&xf_, g_xf);
    cudaGetSymbolAddress((void**)&xh_, g_xh);
    cudaGetSymbolAddress((void**)&xl_, g_xl);
    cudaGetSymbolAddress((void**)&oh_, g_oh);
    cudaGetSymbolAddress((void**)&ol_, g_ol);
    cudaGetSymbolAddress((void**)&gh_, g_gh);
    cudaGetSymbolAddress((void**)&gl_, g_gl);
    cudaGetSymbolAddress((void**)&qh_, g_qh); cudaGetSymbolAddress((void**)&ql_, g_ql);
    cudaGetSymbolAddress((void**)&kh_, g_kh); cudaGetSymbolAddress((void**)&kl_, g_kl);
    cudaGetSymbolAddress((void**)&vh_, g_vh); cudaGetSymbolAddress((void**)&vl_, g_vl);
    cudaGetSymbolAddress((void**)&wqkvh_, g_wqkvh); cudaGetSymbolAddress((void**)&wqkvl_, g_wqkvl);
    cudaGetSymbolAddress((void**)&w13h_, g_w13h); cudaGetSymbolAddress((void**)&w13l_, g_w13l);
    cudaGetSymbolAddress((void**)&woh_, g_woh); cudaGetSymbolAddress((void**)&wol_, g_wol);
    cudaGetSymbolAddress((void**)&w2h_, g_w2h); cudaGetSymbolAddress((void**)&w2l_, g_w2l);

    static int smem_set = 0;
    if (!smem_set) {
        cudaFuncSetAttribute(gemm_bf16x3_kernel<0>,
                             cudaFuncAttributeMaxDynamicSharedMemorySize, SMEM_BYTES);
        cudaFuncSetAttribute(gemm_bf16x3_kernel<1>,
                             cudaFuncAttributeMaxDynamicSharedMemorySize, SMEM_BYTES);
        cudaFuncSetAttribute(gemm_bf16x3_kernel<2>,
                             cudaFuncAttributeMaxDynamicSharedMemorySize, SMEM_BYTES);
        smem_set = 1;
    }

    {
        dim3 grid((unsigned)(PACK_TOTAL / 256), 1, NL);
        pack_all_kernel<<<grid, 256>>>(Wq, Wk, Wv, W1, W3, Wo, W2,
                                       wqkvh_, wqkvl_, w13h_, w13l_,
                                       woh_, wol_, w2h_, w2l_);
    }

    rope_table_kernel<<<(S * 32 + 255) / 256, 256>>>(cos_, sin_);
    embed_kernel<<<(S * D) / 256, 256>>>(tokens, tok_emb, h_);

    const dim3 gQKV(3 * D / GBN, S / GBM);   // (24, 16)
    const dim3 gDD(D / GBN, S / GBM);        // (8, 16)
    const dim3 gW13(2 * HFF / GBN, S / GBM); // (44, 16)

    for (int l = 0; l < NL; l++) {
        size_t offQKV = (size_t)l * 3 * D * D;
        size_t offDD  = (size_t)l * D * D;
        size_t off13  = (size_t)l * 2 * D * HFF;
        size_t offFD  = (size_t)l * HFF * D;

        rmsnorm_split_kernel<<<S, 256>>>(h_, anw + (size_t)l * D, xh_, xl_);

        gemm_bf16x3_kernel<1><<<gQKV, 256, SMEM_BYTES>>>(
            xh_, xl_, wqkvh_ + offQKV, wqkvl_ + offQKV, nullptr, nullptr,
            qh_, ql_, kh_, kl_, vh_, vl_, cos_, sin_, S, 3 * D, D);

        attn_mma_kernel<<<dim3(S / 64, NH), 128>>>(qh_, ql_, kh_, kl_, vh_, vl_, oh_, ol_);

        gemm_bf16x3_kernel<0><<<gDD, 256, SMEM_BYTES>>>(
            oh_, ol_, woh_ + offDD, wol_ + offDD, h_, h_,
            nullptr, nullptr, nullptr, nullptr, nullptr, nullptr, nullptr, nullptr, S, D, D);

        rmsnorm_split_kernel<<<S, 256>>>(h_, fnw + (size_t)l * D, xh_, xl_);

        gemm_bf16x3_kernel<2><<<gW13, 256, SMEM_BYTES>>>(
            xh_, xl_, w13h_ + off13, w13l_ + off13, nullptr, nullptr,
            gh_, gl_, nullptr, nullptr, nullptr, nullptr, nullptr, nullptr, S, 2 * HFF, D);

        gemm_bf16x3_kernel<0><<<gDD, 256, SMEM_BYTES>>>(
            gh_, gl_, w2h_ + offFD, w2l_ + offFD, h_, h_,
            nullptr, nullptr, nullptr, nullptr, nullptr, nullptr, nullptr, nullptr, S, D, HFF);
    }

    rmsnorm_kernel<<<1, 256>>>(h_ + (size_t)(S - 1) * D, finw, xf_);
    logits_kernel<<<NV / 256, 256>>>(xf_, Wout, out);
}

// round 13
// speedup vs baseline: 1.0806x; 1.0085x over previous
#include <cuda_runtime.h>
#include <cuda_bf16.h>
#include <math.h>
#include <stdint.h>

// ---------------- Problem constants ----------------
#define S    2048
#define D    1024
#define NH   16
#define HD   64
#define HFF  2816
#define NV   32000
#define NL   4

typedef __nv_bfloat16 bf16;

// ---------------- Device scratch ----------------
__device__ float g_h[S * D];
__device__ float g_cos[S * 32];
__device__ float g_sin[S * 32];
__device__ float g_xf[D];

__device__ __align__(16) bf16 g_xh[S * D],  g_xl[S * D];
__device__ __align__(16) bf16 g_oh[S * D],  g_ol[S * D];
__device__ __align__(16) bf16 g_gh[S * HFF], g_gl[S * HFF];
__device__ __align__(16) bf16 g_qh[S * D], g_ql[S * D];
__device__ __align__(16) bf16 g_kh[S * D], g_kl[S * D];
__device__ __align__(16) bf16 g_vh[S * D], g_vl[S * D];

__device__ __align__(16) bf16 g_wqkvh[NL * D * 3 * D], g_wqkvl[NL * D * 3 * D];
__device__ __align__(16) bf16 g_w13h[NL * D * 2 * HFF], g_w13l[NL * D * 2 * HFF];
__device__ __align__(16) bf16 g_woh[NL * D * D], g_wol[NL * D * D];
__device__ __align__(16) bf16 g_w2h[NL * HFF * D], g_w2l[NL * HFF * D];

// ---------------- small helpers ----------------
__device__ __forceinline__ void split1(float v, bf16& h, bf16& l) {
    h = __float2bfloat16(v);
    l = __float2bfloat16(v - __bfloat162float(h));
}
__device__ __forceinline__ void split2pack(float x, float y, unsigned& hp, unsigned& lp) {
    bf16 hx = __float2bfloat16(x), hy = __float2bfloat16(y);
    float lx = x - __bfloat162float(hx), ly = y - __bfloat162float(hy);
    bf16 lxb = __float2bfloat16(lx), lyb = __float2bfloat16(ly);
    hp = (unsigned)(*(unsigned short*)&hx) | ((unsigned)(*(unsigned short*)&hy) << 16);
    lp = (unsigned)(*(unsigned short*)&lxb) | ((unsigned)(*(unsigned short*)&lyb) << 16);
}

// ---------------- ONE fused pack+split kernel for all weights ----------------
#define PDD (D * D / 2)
#define PDF (D * HFF / 2)
__global__ void pack_all_kernel(
    const float* __restrict__ Wq, const float* __restrict__ Wk, const float* __restrict__ Wv,
    const float* __restrict__ W1, const float* __restrict__ W3,
    const float* __restrict__ Wo, const float* __restrict__ W2,
    bf16* __restrict__ qkvh, bf16* __restrict__ qkvl,
    bf16* __restrict__ w13h, bf16* __restrict__ w13l,
    bf16* __restrict__ woh, bf16* __restrict__ wol,
    bf16* __restrict__ w2h, bf16* __restrict__ w2l) {
    const int l = blockIdx.z;
    long idx = (long)blockIdx.x * 256 + threadIdx.x;

    if (idx < 3L * PDD) {
        int seg = (int)(idx / PDD);
        int r = (int)(idx % PDD);
        const float* src = (seg == 0 ? Wq : seg == 1 ? Wk : Wv) + (size_t)l * D * D;
        int k = r / (D / 2), n = (r % (D / 2)) * 2;
        float2 v = *(const float2*)(src + (size_t)k * D + n);
        unsigned hp, lp; split2pack(v.x, v.y, hp, lp);
        size_t o = (size_t)l * 3 * D * D + (size_t)k * 3 * D + seg * D + n;
        *(unsigned*)(qkvh + o) = hp;
        *(unsigned*)(qkvl + o) = lp;
        return;
    }
    idx -= 3L * PDD;
    if (idx < 2L * PDF) {
        int seg = (int)(idx / PDF);
        int r = (int)(idx % PDF);
        const float* src = (seg == 0 ? W1 : W3) + (size_t)l * D * HFF;
        int k = r / (HFF / 2), n = (r % (HFF / 2)) * 2;
        float2 v = *(const float2*)(src + (size_t)k * HFF + n);
        bf16 h, lo;
        size_t o = (size_t)l * 2 * D * HFF + (size_t)k * 2 * HFF + seg + 2 * n;
        split1(v.x, h, lo); w13h[o] = h; w13l[o] = lo;
        split1(v.y, h, lo); w13h[o + 2] = h; w13l[o + 2] = lo;
        return;
    }
    idx -= 2L * PDF;
    if (idx < PDD) {
        const float* src = Wo + (size_t)l * D * D;
        int k = (int)(idx / (D / 2)), n = (int)(idx % (D / 2)) * 2;
        float2 v = *(const float2*)(src + (size_t)k * D + n);
        unsigned hp, lp; split2pack(v.x, v.y, hp, lp);
        size_t o = (size_t)l * D * D + (size_t)k * D + n;
        *(unsigned*)(woh + o) = hp;
        *(unsigned*)(wol + o) = lp;
        return;
    }
    idx -= PDD;
    {
        const float* src = W2 + (size_t)l * HFF * D;
        int k = (int)(idx / (D / 2)), n = (int)(idx % (D / 2)) * 2;
        float2 v = *(const float2*)(src + (size_t)k * D + n);
        unsigned hp, lp; split2pack(v.x, v.y, hp, lp);
        size_t o = (size_t)l * HFF * D + (size_t)k * D + n;
        *(unsigned*)(w2h + o) = hp;
        *(unsigned*)(w2l + o) = lp;
    }
}
#define PACK_TOTAL (4L * PDD + 3L * PDF)

// ---------------- RoPE table ----------------
__global__ void rope_table_kernel(float* ct, float* st) {
    int idx = blockIdx.x * 256 + threadIdx.x;
    if (idx >= S * 32) return;
    int pos = idx >> 5;
    int i = idx & 31;
    float inv = powf(10000.0f, -((float)(2 * i) / (float)HD));
    float ang = (float)pos * inv;
    float s, c;
    sincosf(ang, &s, &c);
    ct[idx] = c;
    st[idx] = s;
}

// ---------------- Embedding gather ----------------
__global__ void embed_kernel(const int* __restrict__ tokens,
                             const float* __restrict__ emb,
                             float* __restrict__ h) {
    int idx = blockIdx.x * 256 + threadIdx.x;
    int s = idx >> 10;
    int d = idx & 1023;
    h[idx] = emb[(size_t)tokens[s] * D + d];
}

// ---------------- RMSNorm -> split bf16 hi/lo ----------------
__global__ void rmsnorm_split_kernel(const float* __restrict__ in,
                                     const float* __restrict__ w,
                                     bf16* __restrict__ oh, bf16* __restrict__ ol) {
    const float* r = in + (size_t)blockIdx.x * D;
    bf16* ph = oh + (size_t)blockIdx.x * D;
    bf16* pl = ol + (size_t)blockIdx.x * D;
    int t = threadIdx.x;
    float v[4];
    float ss = 0.f;
#pragma unroll
    for (int i = 0; i < 4; i++) { v[i] = r[t + i * 256]; ss += v[i] * v[i]; }
#pragma unroll
    for (int off = 16; off; off >>= 1) ss += __shfl_xor_sync(0xffffffffu, ss, off);
    __shared__ float red[8];
    if ((t & 31) == 0) red[t >> 5] = ss;
    __syncthreads();
    if (t < 8) {
        float x = red[t];
#pragma unroll
        for (int off = 4; off; off >>= 1) x += __shfl_xor_sync(0xffu, x, off);
        if (t == 0) red[0] = x;
    }
    __syncthreads();
    float scale = rsqrtf(red[0] * (1.0f / (float)D) + 1e-6f);
#pragma unroll
    for (int i = 0; i < 4; i++) {
        float rv = v[i] * scale * w[t + i * 256];
        bf16 h, l; split1(rv, h, l);
        ph[t + i * 256] = h;
        pl[t + i * 256] = l;
    }
}

// ---------------- plain fp32 RMSNorm (final row) ----------------
__global__ void rmsnorm_kernel(const float* __restrict__ in,
                               const float* __restrict__ w,
                               float* __restrict__ out) {
    const float* r = in;
    int t = threadIdx.x;
    float v[4];
    float ss = 0.f;
#pragma unroll
    for (int i = 0; i < 4; i++) { v[i] = r[t + i * 256]; ss += v[i] * v[i]; }
#pragma unroll
    for (int off = 16; off; off >>= 1) ss += __shfl_xor_sync(0xffffffffu, ss, off);
    __shared__ float red[8];
    if ((t & 31) == 0) red[t >> 5] = ss;
    __syncthreads();
    if (t < 8) {
        float x = red[t];
#pragma unroll
        for (int off = 4; off; off >>= 1) x += __shfl_xor_sync(0xffu, x, off);
        if (t == 0) red[0] = x;
    }
    __syncthreads();
    float scale = rsqrtf(red[0] * (1.0f / (float)D) + 1e-6f);
#pragma unroll
    for (int i = 0; i < 4; i++) out[t + i * 256] = v[i] * scale * w[t + i * 256];
}

// ---------------- MMA helpers ----------------
#define LDSM4(r0, r1, r2, r3, addr)                                          \
    asm volatile("ldmatrix.sync.aligned.m8n8.x4.shared.b16 {%0,%1,%2,%3},[%4];" \
                 : "=r"(r0), "=r"(r1), "=r"(r2), "=r"(r3) : "r"(addr))
#define LDSM4T(r0, r1, r2, r3, addr)                                         \
    asm volatile("ldmatrix.sync.aligned.m8n8.x4.trans.shared.b16 {%0,%1,%2,%3},[%4];" \
                 : "=r"(r0), "=r"(r1), "=r"(r2), "=r"(r3) : "r"(addr))
#define CP_ASYNC16(saddr, gaddr)                                             \
    asm volatile("cp.async.cg.shared.global [%0],[%1],16;" :: "r"(saddr), "l"(gaddr))
#define CP_COMMIT() asm volatile("cp.async.commit_group;" ::: "memory")
#define CP_WAIT2()  asm volatile("cp.async.wait_group 2;" ::: "memory")
#define CP_WAIT0()  asm volatile("cp.async.wait_group 0;" ::: "memory")

__device__ __forceinline__ void mma16816(float* c, const unsigned* a, const unsigned* b) {
    asm volatile(
        "mma.sync.aligned.m16n8k16.row.col.f32.bf16.bf16.f32 "
        "{%0,%1,%2,%3},{%4,%5,%6,%7},{%8,%9},{%0,%1,%2,%3};"
        : "+f"(c[0]), "+f"(c[1]), "+f"(c[2]), "+f"(c[3])
        : "r"(a[0]), "r"(a[1]), "r"(a[2]), "r"(a[3]), "r"(b[0]), "r"(b[1]));
}

// ---------------- bf16x3 GEMM: persistent CTAs, cp.async 4-stage, reg-double-buffered ----------------
#define GBM 128
#define GBN 128
#define GBK 32
#define NSTAGE 4
#define A_BUF_BYTES 10240
#define B_BUF_BYTES 8704
#define A_STAGE_BYTES 20480
#define STAGE_BYTES 37888
#define SMEM_BYTES (NSTAGE * STAGE_BYTES)
#define GEMM_GRID 148

extern __shared__ char gsmem[];

template <int MODE>
__global__ __launch_bounds__(256) void gemm_bf16x3_kernel(
    const bf16* __restrict__ Ah, const bf16* __restrict__ Al,
    const bf16* __restrict__ Bh, const bf16* __restrict__ Bl,
    const float* __restrict__ RES, float* __restrict__ C,
    bf16* __restrict__ O1h, bf16* __restrict__ O1l,
    bf16* __restrict__ O2h, bf16* __restrict__ O2l,
    bf16* __restrict__ O3h, bf16* __restrict__ O3l,
    const float* __restrict__ ct, const float* __restrict__ st,
    int M, int N, int K) {
    const int tid  = threadIdx.x;
    const int warp = tid >> 5;
    const int lane = tid & 31;
    const int wm   = (warp >> 2) * 64;
    const int wn   = (warp & 3) * 32;
    const int grp  = lane >> 3;
    const int rin  = lane & 7;

    const uint32_t sBase = (uint32_t)__cvta_generic_to_shared(gsmem);
    const uint32_t laneA = (uint32_t)((((grp & 1) << 3) + rin) * 80 + ((grp >> 1) << 4));
    const uint32_t laneB = (uint32_t)((((grp & 1) << 3) + rin) * 272 + (((grp >> 1) << 3) + wn) * 2);

    const int KT = K / GBK;
    const int nbn = N / GBN;
    const int tiles = (M / GBM) * nbn;

    int bm, bn;   // current tile origin (captured by reference in lambdas)

    auto issue = [&](int kt, int stage) {
        const uint32_t stOff = sBase + stage * STAGE_BYTES;
        const int kOff = kt * GBK;
#pragma unroll
        for (int i = 0; i < 4; i++) {
            int c = tid + 256 * i;
            int buf = c >> 9, rem = c & 511;
            int m = rem >> 2, kq = rem & 3;
            const bf16* g = (buf ? Al : Ah) + (size_t)(bm + m) * K + kOff + kq * 8;
            uint32_t sa = stOff + buf * A_BUF_BYTES + m * 80 + kq * 16;
            CP_ASYNC16(sa, g);
        }
#pragma unroll
        for (int i = 0; i < 4; i++) {
            int c = tid + 256 * i;
            int buf = c >> 9, rem = c & 511;
            int kk = rem >> 4, nq = rem & 15;
            const bf16* g = (buf ? Bl : Bh) + (size_t)(kOff + kk) * N + bn + nq * 8;
            uint32_t sa = stOff + A_STAGE_BYTES + buf * B_BUF_BYTES + kk * 272 + nq * 16;
            CP_ASYNC16(sa, g);
        }
    };

    auto load_frags = [&](unsigned (&a)[2][4][4], unsigned (&b)[2][4][2],
                          uint32_t stOff, int ks) {
#pragma unroll
        for (int buf = 0; buf < 2; buf++) {
            uint32_t aS = stOff + buf * A_BUF_BYTES + laneA + ks * 32;
#pragma unroll
            for (int mt = 0; mt < 4; mt++) {
                uint32_t addr = aS + (wm + mt * 16) * 80;
                LDSM4(a[buf][mt][0], a[buf][mt][1], a[buf][mt][2], a[buf][mt][3], addr);
            }
            uint32_t bS = stOff + A_STAGE_BYTES + buf * B_BUF_BYTES + laneB + ks * 4352;
#pragma unroll
            for (int nj = 0; nj < 2; nj++) {
                uint32_t addr = bS + nj * 32;
                LDSM4T(b[buf][2 * nj][0], b[buf][2 * nj][1],
                       b[buf][2 * nj + 1][0], b[buf][2 * nj + 1][1], addr);
            }
        }
    };

    for (int tile = blockIdx.x; tile < tiles; tile += GEMM_GRID) {
        bm = (tile / nbn) * GBM;
        bn = (tile % nbn) * GBN;

        float acc[4][4][4];
#pragma unroll
        for (int mi = 0; mi < 4; mi++)
#pragma unroll
            for (int ni = 0; ni < 4; ni++)
#pragma unroll
                for (int j = 0; j < 4; j++) acc[mi][ni][j] = 0.f;

        auto do_mma = [&](unsigned (&a)[2][4][4], unsigned (&b)[2][4][2]) {
#pragma unroll
            for (int mt = 0; mt < 4; mt++)
#pragma unroll
                for (int nt = 0; nt < 4; nt++)
                    mma16816(acc[mt][nt], a[0][mt], b[0][nt]);
#pragma unroll
            for (int mt = 0; mt < 4; mt++)
#pragma unroll
                for (int nt = 0; nt < 4; nt++)
                    mma16816(acc[mt][nt], a[0][mt], b[1][nt]);
#pragma unroll
            for (int mt = 0; mt < 4; mt++)
#pragma unroll
                for (int nt = 0; nt < 4; nt++)
                    mma16816(acc[mt][nt], a[1][mt], b[0][nt]);
        };

        unsigned aX[2][4][4], bX[2][4][2];
        unsigned aY[2][4][4], bY[2][4][2];

        issue(0, 0); CP_COMMIT();
        issue(1, 1); CP_COMMIT();
        issue(2, 2); CP_COMMIT();
        CP_WAIT2();
        __syncthreads();
        load_frags(aX, bX, sBase, 0);

        for (int kt = 0; kt < KT; kt++) {
            const uint32_t stOff = sBase + (kt % NSTAGE) * STAGE_BYTES;
            load_frags(aY, bY, stOff, 1);
            do_mma(aX, bX);
            if (kt + 3 < KT) issue(kt + 3, (kt + 3) % NSTAGE);
            CP_COMMIT();
            CP_WAIT2();
            __syncthreads();
            if (kt + 1 < KT)
                load_frags(aX, bX, sBase + ((kt + 1) % NSTAGE) * STAGE_BYTES, 0);
            do_mma(aY, bY);
        }
        CP_WAIT0();        // drain empty groups before next tile reuses stages
        __syncthreads();

        // ---- fused epilogue ----
        const int r0 = bm + wm + (lane >> 2);
        const int c0 = bn + wn + (lane & 3) * 2;
#pragma unroll
        for (int mt = 0; mt < 4; mt++)
#pragma unroll
            for (int nt = 0; nt < 4; nt++) {
                const int col = c0 + nt * 8;
#pragma unroll
                for (int rp = 0; rp < 2; rp++) {
                    const int row = r0 + mt * 16 + rp * 8;
                    float2 v = make_float2(acc[mt][nt][2 * rp], acc[mt][nt][2 * rp + 1]);
                    if (MODE == 0) {
                        if (RES) {
                            float2 a0 = *(const float2*)(RES + (size_t)row * N + col);
                            v.x += a0.x; v.y += a0.y;
                        }
                        *(float2*)(C + (size_t)row * N + col) = v;
                    } else if (MODE == 1) {
                        const int seg = col >> 10;
                        const int d = col & 1023;
                        if (seg < 2) {
                            const int i = (d & 63) >> 1;
                            float c = ct[row * 32 + i];
                            float s = st[row * 32 + i];
                            float a0 = v.x * c - v.y * s;
                            float b0 = v.x * s + v.y * c;
                            v.x = a0; v.y = b0;
                        }
                        unsigned hp, lp;
                        split2pack(v.x, v.y, hp, lp);
                        bf16* oh = (seg == 0) ? O1h : (seg == 1) ? O2h : O3h;
                        bf16* ol = (seg == 0) ? O1l : (seg == 1) ? O2l : O3l;
                        *(unsigned*)(oh + (size_t)row * D + d) = hp;
                        *(unsigned*)(ol + (size_t)row * D + d) = lp;
                    } else {
                        const int j = col >> 1;
                        float z = v.x;
                        float sig = 1.0f / (1.0f + __expf(-z));
                        float r = z * sig * v.y;
                        bf16 h, l; split1(r, h, l);
                        O1h[(size_t)row * HFF + j] = h;
                        O1l[(size_t)row * HFF + j] = l;
                    }
                }
            }
        __syncthreads();   // epilogue done before next tile's cp.async overwrites
    }
}

// ---------------- Tensor-core flash attention (R11: 128 thr, 64-q tiles, 3-pass) ----------------
#define AP 72   // smem row pitch in halfs (144B)

__global__ __launch_bounds__(128) void attn_mma_kernel(
    const bf16* __restrict__ Qh, const bf16* __restrict__ Ql,
    const bf16* __restrict__ Kh, const bf16* __restrict__ Kl,
    const bf16* __restrict__ Vh, const bf16* __restrict__ Vl,
    bf16* __restrict__ Oh, bf16* __restrict__ Ol) {
    __shared__ __align__(16) bf16 sK[2][64 * AP];
    __shared__ __align__(16) bf16 sV[2][64 * AP];

    const int qt   = gridDim.x - 1 - blockIdx.x;   // longest-first
    const int head = blockIdx.y;
    const int tid  = threadIdx.x;
    const int warp = tid >> 5;
    const int lane = tid & 31;
    const int grp  = lane >> 3;
    const int rin  = lane & 7;
    const int wq   = warp * 16;

    {
        const bf16* qsrc[2] = {Qh, Ql};
#pragma unroll
        for (int c = tid; c < 1024; c += 128) {
            int buf = c >> 9, rem = c & 511;
            int row = rem >> 3, col8 = rem & 7;
            *(uint4*)&sK[buf][row * AP + col8 * 8] =
                *(const uint4*)(qsrc[buf] + (size_t)(qt * 64 + row) * D + head * HD + col8 * 8);
        }
    }
    __syncthreads();

    unsigned aQ[2][4][4];
    {
        uint32_t b0 = (uint32_t)__cvta_generic_to_shared(&sK[0][0]);
        uint32_t b1 = (uint32_t)__cvta_generic_to_shared(&sK[1][0]);
        uint32_t laneOff = (uint32_t)(((wq + ((grp & 1) << 3) + rin) * AP + ((grp >> 1) << 3)) << 1);
#pragma unroll
        for (int kc = 0; kc < 4; kc++) {
            LDSM4(aQ[0][kc][0], aQ[0][kc][1], aQ[0][kc][2], aQ[0][kc][3], b0 + laneOff + kc * 32);
            LDSM4(aQ[1][kc][0], aQ[1][kc][1], aQ[1][kc][2], aQ[1][kc][3], b1 + laneOff + kc * 32);
        }
    }

    float o[8][4];
#pragma unroll
    for (int nt = 0; nt < 8; nt++)
#pragma unroll
        for (int j = 0; j < 4; j++) o[nt][j] = 0.f;
    float m0 = -1e30f, m1 = -1e30f, l0 = 0.f, l1 = 0.f;
    const float scale = 0.125f;

    const uint32_t sK0 = (uint32_t)__cvta_generic_to_shared(&sK[0][0]);
    const uint32_t sK1 = (uint32_t)__cvta_generic_to_shared(&sK[1][0]);
    const uint32_t sV0 = (uint32_t)__cvta_generic_to_shared(&sV[0][0]);
    const uint32_t sV1 = (uint32_t)__cvta_generic_to_shared(&sV[1][0]);

    const int r0g = qt * 64 + wq + (lane >> 2);
    const int r1g = r0g + 8;

    for (int kt = 0; kt <= qt; kt++) {
        __syncthreads();
        {
            const bf16* src[4] = {Kh, Kl, Vh, Vl};
            bf16* dst[4] = {sK[0], sK[1], sV[0], sV[1]};
#pragma unroll
            for (int c = tid; c < 2048; c += 128) {
                int which = c >> 9, rem = c & 511;
                int row = rem >> 3, col8 = rem & 7;
                *(uint4*)&dst[which][row * AP + col8 * 8] =
                    *(const uint4*)(src[which] + (size_t)(kt * 64 + row) * D + head * HD + col8 * 8);
            }
        }
        __syncthreads();

        float s[8][4];
#pragma unroll
        for (int nt = 0; nt < 8; nt++)
#pragma unroll
            for (int j = 0; j < 4; j++) s[nt][j] = 0.f;

#pragma unroll
        for (int kc = 0; kc < 4; kc++) {
            unsigned bh[8][2], bl[8][2];
#pragma unroll
            for (int np = 0; np < 4; np++) {
                uint32_t off = (uint32_t)(((np * 16 + ((grp >> 1) << 3) + rin) * AP
                                           + kc * 16 + ((grp & 1) << 3)) << 1);
                LDSM4(bh[2 * np][0], bh[2 * np][1], bh[2 * np + 1][0], bh[2 * np + 1][1], sK0 + off);
                LDSM4(bl[2 * np][0], bl[2 * np][1], bl[2 * np + 1][0], bl[2 * np + 1][1], sK1 + off);
            }
#pragma unroll
            for (int nt = 0; nt < 8; nt++) mma16816(s[nt], aQ[0][kc], bh[nt]);
#pragma unroll
            for (int nt = 0; nt < 8; nt++) mma16816(s[nt], aQ[0][kc], bl[nt]);
#pragma unroll
            for (int nt = 0; nt < 8; nt++) mma16816(s[nt], aQ[1][kc], bh[nt]);
        }

        const bool diag = (kt == qt);
#pragma unroll
        for (int nt = 0; nt < 8; nt++) {
            int c0g = kt * 64 + nt * 8 + (lane & 3) * 2;
            s[nt][0] *= scale; s[nt][1] *= scale;
            s[nt][2] *= scale; s[nt][3] *= scale;
            if (diag) {
                if (c0g     > r0g) s[nt][0] = -1e30f;
                if (c0g + 1 > r0g) s[nt][1] = -1e30f;
                if (c0g     > r1g) s[nt][2] = -1e30f;
                if (c0g + 1 > r1g) s[nt][3] = -1e30f;
            }
        }

        float mx0 = -1e30f, mx1 = -1e30f;
#pragma unroll
        for (int nt = 0; nt < 8; nt++) {
            mx0 = fmaxf(mx0, fmaxf(s[nt][0], s[nt][1]));
            mx1 = fmaxf(mx1, fmaxf(s[nt][2], s[nt][3]));
        }
        mx0 = fmaxf(mx0, __shfl_xor_sync(0xffffffffu, mx0, 1));
        mx0 = fmaxf(mx0, __shfl_xor_sync(0xffffffffu, mx0, 2));
        mx1 = fmaxf(mx1, __shfl_xor_sync(0xffffffffu, mx1, 1));
        mx1 = fmaxf(mx1, __shfl_xor_sync(0xffffffffu, mx1, 2));
        float mn0 = fmaxf(m0, mx0), mn1 = fmaxf(m1, mx1);
        float cr0 = __expf(m0 - mn0), cr1 = __expf(m1 - mn1);
        m0 = mn0; m1 = mn1;
        float rs0 = 0.f, rs1 = 0.f;
#pragma unroll
        for (int nt = 0; nt < 8; nt++) {
            s[nt][0] = __expf(s[nt][0] - mn0); rs0 += s[nt][0];
            s[nt][1] = __expf(s[nt][1] - mn0); rs0 += s[nt][1];
            s[nt][2] = __expf(s[nt][2] - mn1); rs1 += s[nt][2];
            s[nt][3] = __expf(s[nt][3] - mn1); rs1 += s[nt][3];
        }
        l0 = l0 * cr0 + rs0;
        l1 = l1 * cr1 + rs1;
#pragma unroll
        for (int nt = 0; nt < 8; nt++) {
            o[nt][0] *= cr0; o[nt][1] *= cr0;
            o[nt][2] *= cr1; o[nt][3] *= cr1;
        }

#pragma unroll
        for (int kc = 0; kc < 4; kc++) {
            int t0 = 2 * kc, t1 = 2 * kc + 1;
            unsigned ah[4], al[4];
            split2pack(s[t0][0], s[t0][1], ah[0], al[0]);
            split2pack(s[t0][2], s[t0][3], ah[1], al[1]);
            split2pack(s[t1][0], s[t1][1], ah[2], al[2]);
            split2pack(s[t1][2], s[t1][3], ah[3], al[3]);

            unsigned bvh[8][2], bvl[8][2];
#pragma unroll
            for (int np = 0; np < 4; np++) {
                uint32_t off = (uint32_t)(((kc * 16 + ((grp & 1) << 3) + rin) * AP
                                           + np * 16 + ((grp >> 1) << 3)) << 1);
                LDSM4T(bvh[2 * np][0], bvh[2 * np][1], bvh[2 * np + 1][0], bvh[2 * np + 1][1], sV0 + off);
                LDSM4T(bvl[2 * np][0], bvl[2 * np][1], bvl[2 * np + 1][0], bvl[2 * np + 1][1], sV1 + off);
            }
#pragma unroll
            for (int nt = 0; nt < 8; nt++) mma16816(o[nt], ah, bvh[nt]);
#pragma unroll
            for (int nt = 0; nt < 8; nt++) mma16816(o[nt], ah, bvl[nt]);
#pragma unroll
            for (int nt = 0; nt < 8; nt++) mma16816(o[nt], al, bvh[nt]);
        }
    }

    l0 += __shfl_xor_sync(0xffffffffu, l0, 1);
    l0 += __shfl_xor_sync(0xffffffffu, l0, 2);
    l1 += __shfl_xor_sync(0xffffffffu, l1, 1);
    l1 += __shfl_xor_sync(0xffffffffu, l1, 2);
    float inv0 = 1.f / l0, inv1 = 1.f / l1;
#pragma unroll
    for (int nt = 0; nt < 8; nt++) {
        int col = head * HD + nt * 8 + (lane & 3) * 2;
        unsigned hp, lp;
        split2pack(o[nt][0] * inv0, o[nt][1] * inv0, hp, lp);
        *(unsigned*)(Oh + (size_t)r0g * D + col) = hp;
        *(unsigned*)(Ol + (size_t)r0g * D + col) = lp;
        split2pack(o[nt][2] * inv1, o[nt][3] * inv1, hp, lp);
        *(unsigned*)(Oh + (size_t)r1g * D + col) = hp;
        *(unsigned*)(Ol + (size_t)r1g * D + col) = lp;
    }
}

// ---------------- Logits ----------------
__global__ void logits_kernel(const float* __restrict__ xf,
                              const float* __restrict__ Wout,
                              float* __restrict__ out) {
    __shared__ float xs[D];
    for (int i = threadIdx.x; i < D; i += 256) xs[i] = xf[i];
    __syncthreads();
    int v = blockIdx.x * 256 + threadIdx.x;
    float acc = 0.f;
#pragma unroll 8
    for (int d = 0; d < D; d++) acc += xs[d] * Wout[(size_t)d * NV + v];
    out[v] = acc;
}

// ---------------- Host launch ----------------
extern "C" void kernel_launch(void* const* d_in, const int* in_sizes, int n_in,
                              void* d_out, int out_size) {
    int bi = 1;
    if (n_in >= 2 && in_sizes[1] == 1) bi = 2;
    const int*   tokens  = (const int*)d_in[0];
    const float* tok_emb = (const float*)d_in[bi + 0];
    const float* Wq      = (const float*)d_in[bi + 1];
    const float* Wk      = (const float*)d_in[bi + 2];
    const float* Wv      = (const float*)d_in[bi + 3];
    const float* Wo      = (const float*)d_in[bi + 4];
    const float* W1      = (const float*)d_in[bi + 5];
    const float* W2      = (const float*)d_in[bi + 6];
    const float* W3      = (const float*)d_in[bi + 7];
    const float* anw     = (const float*)d_in[bi + 8];
    const float* fnw     = (const float*)d_in[bi + 9];
    const float* finw    = (const float*)d_in[bi + 10];
    const float* Wout    = (const float*)d_in[bi + 11];
    float* out = (float*)d_out;

    float *h_, *cos_, *sin_, *xf_;
    bf16 *xh_, *xl_, *oh_, *ol_, *gh_, *gl_;
    bf16 *qh_, *ql_, *kh_, *kl_, *vh_, *vl_;
    bf16 *wqkvh_, *wqkvl_, *w13h_, *w13l_, *woh_, *wol_, *w2h_, *w2l_;

    cudaGetSymbolAddress((void**)&h_,  g_h);
    cudaGetSymbolAddress((void**)&cos_, g_cos);
    cudaGetSymbolAddress((void**)&sin_, g_sin);
    cudaGetSymbolAddress((void**)&xf_, g_xf);
    cudaGetSymbolAddress((void**)&xh_, g_xh);
    cudaGetSymbolAddress((void**)&xl_, g_xl);
    cudaGetSymbolAddress((void**)&oh_, g_oh);
    cudaGetSymbolAddress((void**)&ol_, g_ol);
    cudaGetSymbolAddress((void**)&gh_, g_gh);
    cudaGetSymbolAddress((void**)&gl_, g_gl);
    cudaGetSymbolAddress((void**)&qh_, g_qh); cudaGetSymbolAddress((void**)&ql_, g_ql);
    cudaGetSymbolAddress((void**)&kh_, g_kh); cudaGetSymbolAddress((void**)&kl_, g_kl);
    cudaGetSymbolAddress((void**)&vh_, g_vh); cudaGetSymbolAddress((void**)&vl_, g_vl);
    cudaGetSymbolAddress((void**)&wqkvh_, g_wqkvh); cudaGetSymbolAddress((void**)&wqkvl_, g_wqkvl);
    cudaGetSymbolAddress((void**)&w13h_, g_w13h); cudaGetSymbolAddress((void**)&w13l_, g_w13l);
    cudaGetSymbolAddress((void**)&woh_, g_woh); cudaGetSymbolAddress((void**)&wol_, g_wol);
    cudaGetSymbolAddress((void**)&w2h_, g_w2h); cudaGetSymbolAddress((void**)&w2l_, g_w2l);

    static int smem_set = 0;
    if (!smem_set) {
        cudaFuncSetAttribute(gemm_bf16x3_kernel<0>,
                             cudaFuncAttributeMaxDynamicSharedMemorySize, SMEM_BYTES);
        cudaFuncSetAttribute(gemm_bf16x3_kernel<1>,
                             cudaFuncAttributeMaxDynamicSharedMemorySize, SMEM_BYTES);
        cudaFuncSetAttribute(gemm_bf16x3_kernel<2>,
                             cudaFuncAttributeMaxDynamicSharedMemorySize, SMEM_BYTES);
        smem_set = 1;
    }

    {
        dim3 grid((unsigned)(PACK_TOTAL / 256), 1, NL);
        pack_all_kernel<<<grid, 256>>>(Wq, Wk, Wv, W1, W3, Wo, W2,
                                       wqkvh_, wqkvl_, w13h_, w13l_,
                                       woh_, wol_, w2h_, w2l_);
    }

    rope_table_kernel<<<(S * 32 + 255) / 256, 256>>>(cos_, sin_);
    embed_kernel<<<(S * D) / 256, 256>>>(tokens, tok_emb, h_);

    for (int l = 0; l < NL; l++) {
        size_t offQKV = (size_t)l * 3 * D * D;
        size_t offDD  = (size_t)l * D * D;
        size_t off13  = (size_t)l * 2 * D * HFF;
        size_t offFD  = (size_t)l * HFF * D;

        rmsnorm_split_kernel<<<S, 256>>>(h_, anw + (size_t)l * D, xh_, xl_);

        gemm_bf16x3_kernel<1><<<GEMM_GRID, 256, SMEM_BYTES>>>(
            xh_, xl_, wqkvh_ + offQKV, wqkvl_ + offQKV, nullptr, nullptr,
            qh_, ql_, kh_, kl_, vh_, vl_, cos_, sin_, S, 3 * D, D);

        attn_mma_kernel<<<dim3(S / 64, NH), 128>>>(qh_, ql_, kh_, kl_, vh_, vl_, oh_, ol_);

        gemm_bf16x3_kernel<0><<<GEMM_GRID, 256, SMEM_BYTES>>>(
            oh_, ol_, woh_ + offDD, wol_ + offDD, h_, h_,
            nullptr, nullptr, nullptr, nullptr, nullptr, nullptr, nullptr, nullptr, S, D, D);

        rmsnorm_split_kernel<<<S, 256>>>(h_, fnw + (size_t)l * D, xh_, xl_);

        gemm_bf16x3_kernel<2><<<GEMM_GRID, 256, SMEM_BYTES>>>(
            xh_, xl_, w13h_ + off13, w13l_ + off13, nullptr, nullptr,
            gh_, gl_, nullptr, nullptr, nullptr, nullptr, nullptr, nullptr, S, 2 * HFF, D);

        gemm_bf16x3_kernel<0><<<GEMM_GRID, 256, SMEM_BYTES>>>(
            gh_, gl_, w2h_ + offFD, w2l_ + offFD, h_, h_,
            nullptr, nullptr, nullptr, nullptr, nullptr, nullptr, nullptr, nullptr, S, D, HFF);
    }

    rmsnorm_kernel<<<1, 256>>>(h_ + (size_t)(S - 1) * D, finw, xf_);
    logits_kernel<<<NV / 256, 256>>>(xf_, Wout, out);
}

// round 14
// speedup vs baseline: 1.0837x; 1.0028x over previous
#include <cuda_runtime.h>
#include <cuda_bf16.h>
#include <math.h>
#include <stdint.h>

// ---------------- Problem constants ----------------
#define S    2048
#define D    1024
#define NH   16
#define HD   64
#define HFF  2816
#define NV   32000
#define NL   4

typedef __nv_bfloat16 bf16;

// ---------------- Device scratch ----------------
__device__ float g_h[S * D];
__device__ float g_cos[S * 32];
__device__ float g_sin[S * 32];
__device__ float g_xf[D];

__device__ __align__(16) bf16 g_xh[S * D],  g_xl[S * D];
__device__ __align__(16) bf16 g_oh[S * D],  g_ol[S * D];
__device__ __align__(16) bf16 g_gh[S * HFF], g_gl[S * HFF];
__device__ __align__(16) bf16 g_qh[S * D], g_ql[S * D];
__device__ __align__(16) bf16 g_kh[S * D], g_kl[S * D];
__device__ __align__(16) bf16 g_vh[S * D], g_vl[S * D];

__device__ __align__(16) bf16 g_wqkvh[NL * D * 3 * D], g_wqkvl[NL * D * 3 * D];
__device__ __align__(16) bf16 g_w13h[NL * D * 2 * HFF], g_w13l[NL * D * 2 * HFF];
__device__ __align__(16) bf16 g_woh[NL * D * D], g_wol[NL * D * D];
__device__ __align__(16) bf16 g_w2h[NL * HFF * D], g_w2l[NL * HFF * D];

// ---------------- small helpers ----------------
__device__ __forceinline__ void split1(float v, bf16& h, bf16& l) {
    h = __float2bfloat16(v);
    l = __float2bfloat16(v - __bfloat162float(h));
}
__device__ __forceinline__ void split2pack(float x, float y, unsigned& hp, unsigned& lp) {
    bf16 hx = __float2bfloat16(x), hy = __float2bfloat16(y);
    float lx = x - __bfloat162float(hx), ly = y - __bfloat162float(hy);
    bf16 lxb = __float2bfloat16(lx), lyb = __float2bfloat16(ly);
    hp = (unsigned)(*(unsigned short*)&hx) | ((unsigned)(*(unsigned short*)&hy) << 16);
    lp = (unsigned)(*(unsigned short*)&lxb) | ((unsigned)(*(unsigned short*)&lyb) << 16);
}

// ---------------- ONE fused pack+split kernel for all weights ----------------
#define PDD (D * D / 2)
#define PDF (D * HFF / 2)
__global__ void pack_all_kernel(
    const float* __restrict__ Wq, const float* __restrict__ Wk, const float* __restrict__ Wv,
    const float* __restrict__ W1, const float* __restrict__ W3,
    const float* __restrict__ Wo, const float* __restrict__ W2,
    bf16* __restrict__ qkvh, bf16* __restrict__ qkvl,
    bf16* __restrict__ w13h, bf16* __restrict__ w13l,
    bf16* __restrict__ woh, bf16* __restrict__ wol,
    bf16* __restrict__ w2h, bf16* __restrict__ w2l) {
    const int l = blockIdx.z;
    long idx = (long)blockIdx.x * 256 + threadIdx.x;

    if (idx < 3L * PDD) {
        int seg = (int)(idx / PDD);
        int r = (int)(idx % PDD);
        const float* src = (seg == 0 ? Wq : seg == 1 ? Wk : Wv) + (size_t)l * D * D;
        int k = r / (D / 2), n = (r % (D / 2)) * 2;
        float2 v = *(const float2*)(src + (size_t)k * D + n);
        unsigned hp, lp; split2pack(v.x, v.y, hp, lp);
        size_t o = (size_t)l * 3 * D * D + (size_t)k * 3 * D + seg * D + n;
        *(unsigned*)(qkvh + o) = hp;
        *(unsigned*)(qkvl + o) = lp;
        return;
    }
    idx -= 3L * PDD;
    if (idx < 2L * PDF) {
        int seg = (int)(idx / PDF);
        int r = (int)(idx % PDF);
        const float* src = (seg == 0 ? W1 : W3) + (size_t)l * D * HFF;
        int k = r / (HFF / 2), n = (r % (HFF / 2)) * 2;
        float2 v = *(const float2*)(src + (size_t)k * HFF + n);
        bf16 h, lo;
        size_t o = (size_t)l * 2 * D * HFF + (size_t)k * 2 * HFF + seg + 2 * n;
        split1(v.x, h, lo); w13h[o] = h; w13l[o] = lo;
        split1(v.y, h, lo); w13h[o + 2] = h; w13l[o + 2] = lo;
        return;
    }
    idx -= 2L * PDF;
    if (idx < PDD) {
        const float* src = Wo + (size_t)l * D * D;
        int k = (int)(idx / (D / 2)), n = (int)(idx % (D / 2)) * 2;
        float2 v = *(const float2*)(src + (size_t)k * D + n);
        unsigned hp, lp; split2pack(v.x, v.y, hp, lp);
        size_t o = (size_t)l * D * D + (size_t)k * D + n;
        *(unsigned*)(woh + o) = hp;
        *(unsigned*)(wol + o) = lp;
        return;
    }
    idx -= PDD;
    {
        const float* src = W2 + (size_t)l * HFF * D;
        int k = (int)(idx / (D / 2)), n = (int)(idx % (D / 2)) * 2;
        float2 v = *(const float2*)(src + (size_t)k * D + n);
        unsigned hp, lp; split2pack(v.x, v.y, hp, lp);
        size_t o = (size_t)l * HFF * D + (size_t)k * D + n;
        *(unsigned*)(w2h + o) = hp;
        *(unsigned*)(w2l + o) = lp;
    }
}
#define PACK_TOTAL (4L * PDD + 3L * PDF)

// ---------------- RoPE table ----------------
__global__ void rope_table_kernel(float* ct, float* st) {
    int idx = blockIdx.x * 256 + threadIdx.x;
    if (idx >= S * 32) return;
    int pos = idx >> 5;
    int i = idx & 31;
    float inv = powf(10000.0f, -((float)(2 * i) / (float)HD));
    float ang = (float)pos * inv;
    float s, c;
    sincosf(ang, &s, &c);
    ct[idx] = c;
    st[idx] = s;
}

// ---------------- Embedding gather ----------------
__global__ void embed_kernel(const int* __restrict__ tokens,
                             const float* __restrict__ emb,
                             float* __restrict__ h) {
    int idx = blockIdx.x * 256 + threadIdx.x;
    int s = idx >> 10;
    int d = idx & 1023;
    h[idx] = emb[(size_t)tokens[s] * D + d];
}

// ---------------- RMSNorm -> split bf16 hi/lo ----------------
__global__ void rmsnorm_split_kernel(const float* __restrict__ in,
                                     const float* __restrict__ w,
                                     bf16* __restrict__ oh, bf16* __restrict__ ol) {
    const float* r = in + (size_t)blockIdx.x * D;
    bf16* ph = oh + (size_t)blockIdx.x * D;
    bf16* pl = ol + (size_t)blockIdx.x * D;
    int t = threadIdx.x;
    float v[4];
    float ss = 0.f;
#pragma unroll
    for (int i = 0; i < 4; i++) { v[i] = r[t + i * 256]; ss += v[i] * v[i]; }
#pragma unroll
    for (int off = 16; off; off >>= 1) ss += __shfl_xor_sync(0xffffffffu, ss, off);
    __shared__ float red[8];
    if ((t & 31) == 0) red[t >> 5] = ss;
    __syncthreads();
    if (t < 8) {
        float x = red[t];
#pragma unroll
        for (int off = 4; off; off >>= 1) x += __shfl_xor_sync(0xffu, x, off);
        if (t == 0) red[0] = x;
    }
    __syncthreads();
    float scale = rsqrtf(red[0] * (1.0f / (float)D) + 1e-6f);
#pragma unroll
    for (int i = 0; i < 4; i++) {
        float rv = v[i] * scale * w[t + i * 256];
        bf16 h, l; split1(rv, h, l);
        ph[t + i * 256] = h;
        pl[t + i * 256] = l;
    }
}

// ---------------- plain fp32 RMSNorm (final row) ----------------
__global__ void rmsnorm_kernel(const float* __restrict__ in,
                               const float* __restrict__ w,
                               float* __restrict__ out) {
    const float* r = in;
    int t = threadIdx.x;
    float v[4];
    float ss = 0.f;
#pragma unroll
    for (int i = 0; i < 4; i++) { v[i] = r[t + i * 256]; ss += v[i] * v[i]; }
#pragma unroll
    for (int off = 16; off; off >>= 1) ss += __shfl_xor_sync(0xffffffffu, ss, off);
    __shared__ float red[8];
    if ((t & 31) == 0) red[t >> 5] = ss;
    __syncthreads();
    if (t < 8) {
        float x = red[t];
#pragma unroll
        for (int off = 4; off; off >>= 1) x += __shfl_xor_sync(0xffu, x, off);
        if (t == 0) red[0] = x;
    }
    __syncthreads();
    float scale = rsqrtf(red[0] * (1.0f / (float)D) + 1e-6f);
#pragma unroll
    for (int i = 0; i < 4; i++) out[t + i * 256] = v[i] * scale * w[t + i * 256];
}

// ---------------- MMA helpers ----------------
#define LDSM4(r0, r1, r2, r3, addr)                                          \
    asm volatile("ldmatrix.sync.aligned.m8n8.x4.shared.b16 {%0,%1,%2,%3},[%4];" \
                 : "=r"(r0), "=r"(r1), "=r"(r2), "=r"(r3) : "r"(addr))
#define LDSM4T(r0, r1, r2, r3, addr)                                         \
    asm volatile("ldmatrix.sync.aligned.m8n8.x4.trans.shared.b16 {%0,%1,%2,%3},[%4];" \
                 : "=r"(r0), "=r"(r1), "=r"(r2), "=r"(r3) : "r"(addr))
#define CP_ASYNC16(saddr, gaddr)                                             \
    asm volatile("cp.async.cg.shared.global [%0],[%1],16;" :: "r"(saddr), "l"(gaddr))
#define CP_COMMIT() asm volatile("cp.async.commit_group;" ::: "memory")
#define CP_WAIT2()  asm volatile("cp.async.wait_group 2;" ::: "memory")
#define CP_WAIT0()  asm volatile("cp.async.wait_group 0;" ::: "memory")

__device__ __forceinline__ void mma16816(float* c, const unsigned* a, const unsigned* b) {
    asm volatile(
        "mma.sync.aligned.m16n8k16.row.col.f32.bf16.bf16.f32 "
        "{%0,%1,%2,%3},{%4,%5,%6,%7},{%8,%9},{%0,%1,%2,%3};"
        : "+f"(c[0]), "+f"(c[1]), "+f"(c[2]), "+f"(c[3])
        : "r"(a[0]), "r"(a[1]), "r"(a[2]), "r"(a[3]), "r"(b[0]), "r"(b[1]));
}

// ---------------- bf16x3 GEMM: persistent CTAs, cp.async 4-stage, reg-double-buffered ----------------
#define GBM 128
#define GBN 128
#define GBK 32
#define NSTAGE 4
#define A_BUF_BYTES 10240
#define B_BUF_BYTES 8704
#define A_STAGE_BYTES 20480
#define STAGE_BYTES 37888
#define SMEM_BYTES (NSTAGE * STAGE_BYTES)
#define GEMM_GRID 148

extern __shared__ char gsmem[];

template <int MODE>
__global__ __launch_bounds__(256) void gemm_bf16x3_kernel(
    const bf16* __restrict__ Ah, const bf16* __restrict__ Al,
    const bf16* __restrict__ Bh, const bf16* __restrict__ Bl,
    const float* __restrict__ RES, float* __restrict__ C,
    bf16* __restrict__ O1h, bf16* __restrict__ O1l,
    bf16* __restrict__ O2h, bf16* __restrict__ O2l,
    bf16* __restrict__ O3h, bf16* __restrict__ O3l,
    const float* __restrict__ ct, const float* __restrict__ st,
    int M, int N, int K) {
    const int tid  = threadIdx.x;
    const int warp = tid >> 5;
    const int lane = tid & 31;
    const int wm   = (warp >> 2) * 64;
    const int wn   = (warp & 3) * 32;
    const int grp  = lane >> 3;
    const int rin  = lane & 7;

    const uint32_t sBase = (uint32_t)__cvta_generic_to_shared(gsmem);
    const uint32_t laneA = (uint32_t)((((grp & 1) << 3) + rin) * 80 + ((grp >> 1) << 4));
    const uint32_t laneB = (uint32_t)((((grp & 1) << 3) + rin) * 272 + (((grp >> 1) << 3) + wn) * 2);

    const int KT = K / GBK;
    const int nbn = N / GBN;
    const int tiles = (M / GBM) * nbn;

    int bm, bn;

    auto issue = [&](int kt, int stage) {
        const uint32_t stOff = sBase + stage * STAGE_BYTES;
        const int kOff = kt * GBK;
#pragma unroll
        for (int i = 0; i < 4; i++) {
            int c = tid + 256 * i;
            int buf = c >> 9, rem = c & 511;
            int m = rem >> 2, kq = rem & 3;
            const bf16* g = (buf ? Al : Ah) + (size_t)(bm + m) * K + kOff + kq * 8;
            uint32_t sa = stOff + buf * A_BUF_BYTES + m * 80 + kq * 16;
            CP_ASYNC16(sa, g);
        }
#pragma unroll
        for (int i = 0; i < 4; i++) {
            int c = tid + 256 * i;
            int buf = c >> 9, rem = c & 511;
            int kk = rem >> 4, nq = rem & 15;
            const bf16* g = (buf ? Bl : Bh) + (size_t)(kOff + kk) * N + bn + nq * 8;
            uint32_t sa = stOff + A_STAGE_BYTES + buf * B_BUF_BYTES + kk * 272 + nq * 16;
            CP_ASYNC16(sa, g);
        }
    };

    auto load_frags = [&](unsigned (&a)[2][4][4], unsigned (&b)[2][4][2],
                          uint32_t stOff, int ks) {
#pragma unroll
        for (int buf = 0; buf < 2; buf++) {
            uint32_t aS = stOff + buf * A_BUF_BYTES + laneA + ks * 32;
#pragma unroll
            for (int mt = 0; mt < 4; mt++) {
                uint32_t addr = aS + (wm + mt * 16) * 80;
                LDSM4(a[buf][mt][0], a[buf][mt][1], a[buf][mt][2], a[buf][mt][3], addr);
            }
            uint32_t bS = stOff + A_STAGE_BYTES + buf * B_BUF_BYTES + laneB + ks * 4352;
#pragma unroll
            for (int nj = 0; nj < 2; nj++) {
                uint32_t addr = bS + nj * 32;
                LDSM4T(b[buf][2 * nj][0], b[buf][2 * nj][1],
                       b[buf][2 * nj + 1][0], b[buf][2 * nj + 1][1], addr);
            }
        }
    };

    for (int tile = blockIdx.x; tile < tiles; tile += GEMM_GRID) {
        bm = (tile / nbn) * GBM;
        bn = (tile % nbn) * GBN;

        float acc[4][4][4];
#pragma unroll
        for (int mi = 0; mi < 4; mi++)
#pragma unroll
            for (int ni = 0; ni < 4; ni++)
#pragma unroll
                for (int j = 0; j < 4; j++) acc[mi][ni][j] = 0.f;

        auto do_mma = [&](unsigned (&a)[2][4][4], unsigned (&b)[2][4][2]) {
#pragma unroll
            for (int mt = 0; mt < 4; mt++)
#pragma unroll
                for (int nt = 0; nt < 4; nt++)
                    mma16816(acc[mt][nt], a[0][mt], b[0][nt]);
#pragma unroll
            for (int mt = 0; mt < 4; mt++)
#pragma unroll
                for (int nt = 0; nt < 4; nt++)
                    mma16816(acc[mt][nt], a[0][mt], b[1][nt]);
#pragma unroll
            for (int mt = 0; mt < 4; mt++)
#pragma unroll
                for (int nt = 0; nt < 4; nt++)
                    mma16816(acc[mt][nt], a[1][mt], b[0][nt]);
        };

        unsigned aX[2][4][4], bX[2][4][2];
        unsigned aY[2][4][4], bY[2][4][2];

        issue(0, 0); CP_COMMIT();
        issue(1, 1); CP_COMMIT();
        issue(2, 2); CP_COMMIT();
        CP_WAIT2();
        __syncthreads();
        load_frags(aX, bX, sBase, 0);

        for (int kt = 0; kt < KT; kt++) {
            const uint32_t stOff = sBase + (kt % NSTAGE) * STAGE_BYTES;
            load_frags(aY, bY, stOff, 1);
            do_mma(aX, bX);
            if (kt + 3 < KT) issue(kt + 3, (kt + 3) % NSTAGE);
            CP_COMMIT();
            CP_WAIT2();
            __syncthreads();
            if (kt + 1 < KT)
                load_frags(aX, bX, sBase + ((kt + 1) % NSTAGE) * STAGE_BYTES, 0);
            do_mma(aY, bY);
        }
        CP_WAIT0();
        __syncthreads();

        // ---- fused epilogue ----
        const int r0 = bm + wm + (lane >> 2);
        const int c0 = bn + wn + (lane & 3) * 2;
#pragma unroll
        for (int mt = 0; mt < 4; mt++)
#pragma unroll
            for (int nt = 0; nt < 4; nt++) {
                const int col = c0 + nt * 8;
#pragma unroll
                for (int rp = 0; rp < 2; rp++) {
                    const int row = r0 + mt * 16 + rp * 8;
                    float2 v = make_float2(acc[mt][nt][2 * rp], acc[mt][nt][2 * rp + 1]);
                    if (MODE == 0) {
                        if (RES) {
                            float2 a0 = *(const float2*)(RES + (size_t)row * N + col);
                            v.x += a0.x; v.y += a0.y;
                        }
                        *(float2*)(C + (size_t)row * N + col) = v;
                    } else if (MODE == 1) {
                        const int seg = col >> 10;
                        const int d = col & 1023;
                        if (seg < 2) {
                            const int i = (d & 63) >> 1;
                            float c = ct[row * 32 + i];
                            float s = st[row * 32 + i];
                            float a0 = v.x * c - v.y * s;
                            float b0 = v.x * s + v.y * c;
                            v.x = a0; v.y = b0;
                        }
                        unsigned hp, lp;
                        split2pack(v.x, v.y, hp, lp);
                        bf16* oh = (seg == 0) ? O1h : (seg == 1) ? O2h : O3h;
                        bf16* ol = (seg == 0) ? O1l : (seg == 1) ? O2l : O3l;
                        *(unsigned*)(oh + (size_t)row * D + d) = hp;
                        *(unsigned*)(ol + (size_t)row * D + d) = lp;
                    } else {
                        const int j = col >> 1;
                        float z = v.x;
                        float sig = 1.0f / (1.0f + __expf(-z));
                        float r = z * sig * v.y;
                        bf16 h, l; split1(r, h, l);
                        O1h[(size_t)row * HFF + j] = h;
                        O1l[(size_t)row * HFF + j] = l;
                    }
                }
            }
        __syncthreads();
    }
}

// ---------------- Tensor-core flash attention (Q in smem; regs capped for 3 CTAs/SM) ----------------
#define AP 72   // smem row pitch in halfs (144B)

__global__ __launch_bounds__(128, 3) void attn_mma_kernel(
    const bf16* __restrict__ Qh, const bf16* __restrict__ Ql,
    const bf16* __restrict__ Kh, const bf16* __restrict__ Kl,
    const bf16* __restrict__ Vh, const bf16* __restrict__ Vl,
    bf16* __restrict__ Oh, bf16* __restrict__ Ol) {
    __shared__ __align__(16) bf16 sQ[2][64 * AP];
    __shared__ __align__(16) bf16 sK[2][64 * AP];
    __shared__ __align__(16) bf16 sV[2][64 * AP];

    const int qt   = gridDim.x - 1 - blockIdx.x;   // longest-first
    const int head = blockIdx.y;
    const int tid  = threadIdx.x;
    const int warp = tid >> 5;
    const int lane = tid & 31;
    const int grp  = lane >> 3;
    const int rin  = lane & 7;
    const int wq   = warp * 16;

    {
        const bf16* qsrc[2] = {Qh, Ql};
#pragma unroll
        for (int c = tid; c < 1024; c += 128) {
            int buf = c >> 9, rem = c & 511;
            int row = rem >> 3, col8 = rem & 7;
            *(uint4*)&sQ[buf][row * AP + col8 * 8] =
                *(const uint4*)(qsrc[buf] + (size_t)(qt * 64 + row) * D + head * HD + col8 * 8);
        }
    }

    float o[8][4];
#pragma unroll
    for (int nt = 0; nt < 8; nt++)
#pragma unroll
        for (int j = 0; j < 4; j++) o[nt][j] = 0.f;
    float m0 = -1e30f, m1 = -1e30f, l0 = 0.f, l1 = 0.f;
    const float scale = 0.125f;

    const uint32_t sQ0 = (uint32_t)__cvta_generic_to_shared(&sQ[0][0]);
    const uint32_t sQ1 = (uint32_t)__cvta_generic_to_shared(&sQ[1][0]);
    const uint32_t sK0 = (uint32_t)__cvta_generic_to_shared(&sK[0][0]);
    const uint32_t sK1 = (uint32_t)__cvta_generic_to_shared(&sK[1][0]);
    const uint32_t sV0 = (uint32_t)__cvta_generic_to_shared(&sV[0][0]);
    const uint32_t sV1 = (uint32_t)__cvta_generic_to_shared(&sV[1][0]);
    const uint32_t laneOffQ = (uint32_t)(((wq + ((grp & 1) << 3) + rin) * AP + ((grp >> 1) << 3)) << 1);

    const int r0g = qt * 64 + wq + (lane >> 2);
    const int r1g = r0g + 8;

    for (int kt = 0; kt <= qt; kt++) {
        __syncthreads();
        {
            const bf16* src[4] = {Kh, Kl, Vh, Vl};
            bf16* dst[4] = {sK[0], sK[1], sV[0], sV[1]};
#pragma unroll
            for (int c = tid; c < 2048; c += 128) {
                int which = c >> 9, rem = c & 511;
                int row = rem >> 3, col8 = rem & 7;
                *(uint4*)&dst[which][row * AP + col8 * 8] =
                    *(const uint4*)(src[which] + (size_t)(kt * 64 + row) * D + head * HD + col8 * 8);
            }
        }
        __syncthreads();

        // ---- reload Q fragments (sQ is never overwritten) ----
        unsigned aQ[2][4][4];
#pragma unroll
        for (int kc = 0; kc < 4; kc++) {
            LDSM4(aQ[0][kc][0], aQ[0][kc][1], aQ[0][kc][2], aQ[0][kc][3], sQ0 + laneOffQ + kc * 32);
            LDSM4(aQ[1][kc][0], aQ[1][kc][1], aQ[1][kc][2], aQ[1][kc][3], sQ1 + laneOffQ + kc * 32);
        }

        float s[8][4];
#pragma unroll
        for (int nt = 0; nt < 8; nt++)
#pragma unroll
            for (int j = 0; j < 4; j++) s[nt][j] = 0.f;

#pragma unroll
        for (int kc = 0; kc < 4; kc++) {
            unsigned bh[8][2], bl[8][2];
#pragma unroll
            for (int np = 0; np < 4; np++) {
                uint32_t off = (uint32_t)(((np * 16 + ((grp >> 1) << 3) + rin) * AP
                                           + kc * 16 + ((grp & 1) << 3)) << 1);
                LDSM4(bh[2 * np][0], bh[2 * np][1], bh[2 * np + 1][0], bh[2 * np + 1][1], sK0 + off);
                LDSM4(bl[2 * np][0], bl[2 * np][1], bl[2 * np + 1][0], bl[2 * np + 1][1], sK1 + off);
            }
#pragma unroll
            for (int nt = 0; nt < 8; nt++) mma16816(s[nt], aQ[0][kc], bh[nt]);
#pragma unroll
            for (int nt = 0; nt < 8; nt++) mma16816(s[nt], aQ[0][kc], bl[nt]);
#pragma unroll
            for (int nt = 0; nt < 8; nt++) mma16816(s[nt], aQ[1][kc], bh[nt]);
        }

        const bool diag = (kt == qt);
#pragma unroll
        for (int nt = 0; nt < 8; nt++) {
            int c0g = kt * 64 + nt * 8 + (lane & 3) * 2;
            s[nt][0] *= scale; s[nt][1] *= scale;
            s[nt][2] *= scale; s[nt][3] *= scale;
            if (diag) {
                if (c0g     > r0g) s[nt][0] = -1e30f;
                if (c0g + 1 > r0g) s[nt][1] = -1e30f;
                if (c0g     > r1g) s[nt][2] = -1e30f;
                if (c0g + 1 > r1g) s[nt][3] = -1e30f;
            }
        }

        float mx0 = -1e30f, mx1 = -1e30f;
#pragma unroll
        for (int nt = 0; nt < 8; nt++) {
            mx0 = fmaxf(mx0, fmaxf(s[nt][0], s[nt][1]));
            mx1 = fmaxf(mx1, fmaxf(s[nt][2], s[nt][3]));
        }
        mx0 = fmaxf(mx0, __shfl_xor_sync(0xffffffffu, mx0, 1));
        mx0 = fmaxf(mx0, __shfl_xor_sync(0xffffffffu, mx0, 2));
        mx1 = fmaxf(mx1, __shfl_xor_sync(0xffffffffu, mx1, 1));
        mx1 = fmaxf(mx1, __shfl_xor_sync(0xffffffffu, mx1, 2));
        float mn0 = fmaxf(m0, mx0), mn1 = fmaxf(m1, mx1);
        float cr0 = __expf(m0 - mn0), cr1 = __expf(m1 - mn1);
        m0 = mn0; m1 = mn1;
        float rs0 = 0.f, rs1 = 0.f;
#pragma unroll
        for (int nt = 0; nt < 8; nt++) {
            s[nt][0] = __expf(s[nt][0] - mn0); rs0 += s[nt][0];
            s[nt][1] = __expf(s[nt][1] - mn0); rs0 += s[nt][1];
            s[nt][2] = __expf(s[nt][2] - mn1); rs1 += s[nt][2];
            s[nt][3] = __expf(s[nt][3] - mn1); rs1 += s[nt][3];
        }
        l0 = l0 * cr0 + rs0;
        l1 = l1 * cr1 + rs1;
#pragma unroll
        for (int nt = 0; nt < 8; nt++) {
            o[nt][0] *= cr0; o[nt][1] *= cr0;
            o[nt][2] *= cr1; o[nt][3] *= cr1;
        }

#pragma unroll
        for (int kc = 0; kc < 4; kc++) {
            int t0 = 2 * kc, t1 = 2 * kc + 1;
            unsigned ah[4], al[4];
            split2pack(s[t0][0], s[t0][1], ah[0], al[0]);
            split2pack(s[t0][2], s[t0][3], ah[1], al[1]);
            split2pack(s[t1][0], s[t1][1], ah[2], al[2]);
            split2pack(s[t1][2], s[t1][3], ah[3], al[3]);

            unsigned bvh[8][2], bvl[8][2];
#pragma unroll
            for (int np = 0; np < 4; np++) {
                uint32_t off = (uint32_t)(((kc * 16 + ((grp & 1) << 3) + rin) * AP
                                           + np * 16 + ((grp >> 1) << 3)) << 1);
                LDSM4T(bvh[2 * np][0], bvh[2 * np][1], bvh[2 * np + 1][0], bvh[2 * np + 1][1], sV0 + off);
                LDSM4T(bvl[2 * np][0], bvl[2 * np][1], bvl[2 * np + 1][0], bvl[2 * np + 1][1], sV1 + off);
            }
#pragma unroll
            for (int nt = 0; nt < 8; nt++) mma16816(o[nt], ah, bvh[nt]);
#pragma unroll
            for (int nt = 0; nt < 8; nt++) mma16816(o[nt], ah, bvl[nt]);
#pragma unroll
            for (int nt = 0; nt < 8; nt++) mma16816(o[nt], al, bvh[nt]);
        }
    }

    l0 += __shfl_xor_sync(0xffffffffu, l0, 1);
    l0 += __shfl_xor_sync(0xffffffffu, l0, 2);
    l1 += __shfl_xor_sync(0xffffffffu, l1, 1);
    l1 += __shfl_xor_sync(0xffffffffu, l1, 2);
    float inv0 = 1.f / l0, inv1 = 1.f / l1;
#pragma unroll
    for (int nt = 0; nt < 8; nt++) {
        int col = head * HD + nt * 8 + (lane & 3) * 2;
        unsigned hp, lp;
        split2pack(o[nt][0] * inv0, o[nt][1] * inv0, hp, lp);
        *(unsigned*)(Oh + (size_t)r0g * D + col) = hp;
        *(unsigned*)(Ol + (size_t)r0g * D + col) = lp;
        split2pack(o[nt][2] * inv1, o[nt][3] * inv1, hp, lp);
        *(unsigned*)(Oh + (size_t)r1g * D + col) = hp;
        *(unsigned*)(Ol + (size_t)r1g * D + col) = lp;
    }
}

// ---------------- Logits ----------------
__global__ void logits_kernel(const float* __restrict__ xf,
                              const float* __restrict__ Wout,
                              float* __restrict__ out) {
    __shared__ float xs[D];
    for (int i = threadIdx.x; i < D; i += 256) xs[i] = xf[i];
    __syncthreads();
    int v = blockIdx.x * 256 + threadIdx.x;
    float acc = 0.f;
#pragma unroll 8
    for (int d = 0; d < D; d++) acc += xs[d] * Wout[(size_t)d * NV + v];
    out[v] = acc;
}

// ---------------- Host launch ----------------
extern "C" void kernel_launch(void* const* d_in, const int* in_sizes, int n_in,
                              void* d_out, int out_size) {
    int bi = 1;
    if (n_in >= 2 && in_sizes[1] == 1) bi = 2;
    const int*   tokens  = (const int*)d_in[0];
    const float* tok_emb = (const float*)d_in[bi + 0];
    const float* Wq      = (const float*)d_in[bi + 1];
    const float* Wk      = (const float*)d_in[bi + 2];
    const float* Wv      = (const float*)d_in[bi + 3];
    const float* Wo      = (const float*)d_in[bi + 4];
    const float* W1      = (const float*)d_in[bi + 5];
    const float* W2      = (const float*)d_in[bi + 6];
    const float* W3      = (const float*)d_in[bi + 7];
    const float* anw     = (const float*)d_in[bi + 8];
    const float* fnw     = (const float*)d_in[bi + 9];
    const float* finw    = (const float*)d_in[bi + 10];
    const float* Wout    = (const float*)d_in[bi + 11];
    float* out = (float*)d_out;

    float *h_, *cos_, *sin_, *xf_;
    bf16 *xh_, *xl_, *oh_, *ol_, *gh_, *gl_;
    bf16 *qh_, *ql_, *kh_, *kl_, *vh_, *vl_;
    bf16 *wqkvh_, *wqkvl_, *w13h_, *w13l_, *woh_, *wol_, *w2h_, *w2l_;

    cudaGetSymbolAddress((void**)&h_,  g_h);
    cudaGetSymbolAddress((void**)&cos_, g_cos);
    cudaGetSymbolAddress((void**)&sin_, g_sin);
    cudaGetSymbolAddress((void**)&xf_, g_xf);
    cudaGetSymbolAddress((void**)&xh_, g_xh);
    cudaGetSymbolAddress((void**)&xl_, g_xl);
    cudaGetSymbolAddress((void**)&oh_, g_oh);
    cudaGetSymbolAddress((void**)&ol_, g_ol);
    cudaGetSymbolAddress((void**)&gh_, g_gh);
    cudaGetSymbolAddress((void**)&gl_, g_gl);
    cudaGetSymbolAddress((void**)&qh_, g_qh); cudaGetSymbolAddress((void**)&ql_, g_ql);
    cudaGetSymbolAddress((void**)&kh_, g_kh); cudaGetSymbolAddress((void**)&kl_, g_kl);
    cudaGetSymbolAddress((void**)&vh_, g_vh); cudaGetSymbolAddress((void**)&vl_, g_vl);
    cudaGetSymbolAddress((void**)&wqkvh_, g_wqkvh); cudaGetSymbolAddress((void**)&wqkvl_, g_wqkvl);
    cudaGetSymbolAddress((void**)&w13h_, g_w13h); cudaGetSymbolAddress((void**)&w13l_, g_w13l);
    cudaGetSymbolAddress((void**)&woh_, g_woh); cudaGetSymbolAddress((void**)&wol_, g_wol);
    cudaGetSymbolAddress((void**)&w2h_, g_w2h); cudaGetSymbolAddress((void**)&w2l_, g_w2l);

    static int smem_set = 0;
    if (!smem_set) {
        cudaFuncSetAttribute(gemm_bf16x3_kernel<0>,
                             cudaFuncAttributeMaxDynamicSharedMemorySize, SMEM_BYTES);
        cudaFuncSetAttribute(gemm_bf16x3_kernel<1>,
                             cudaFuncAttributeMaxDynamicSharedMemorySize, SMEM_BYTES);
        cudaFuncSetAttribute(gemm_bf16x3_kernel<2>,
                             cudaFuncAttributeMaxDynamicSharedMemorySize, SMEM_BYTES);
        smem_set = 1;
    }

    {
        dim3 grid((unsigned)(PACK_TOTAL / 256), 1, NL);
        pack_all_kernel<<<grid, 256>>>(Wq, Wk, Wv, W1, W3, Wo, W2,
                                       wqkvh_, wqkvl_, w13h_, w13l_,
                                       woh_, wol_, w2h_, w2l_);
    }

    rope_table_kernel<<<(S * 32 + 255) / 256, 256>>>(cos_, sin_);
    embed_kernel<<<(S * D) / 256, 256>>>(tokens, tok_emb, h_);

    for (int l = 0; l < NL; l++) {
        size_t offQKV = (size_t)l * 3 * D * D;
        size_t offDD  = (size_t)l * D * D;
        size_t off13  = (size_t)l * 2 * D * HFF;
        size_t offFD  = (size_t)l * HFF * D;

        rmsnorm_split_kernel<<<S, 256>>>(h_, anw + (size_t)l * D, xh_, xl_);

        gemm_bf16x3_kernel<1><<<GEMM_GRID, 256, SMEM_BYTES>>>(
            xh_, xl_, wqkvh_ + offQKV, wqkvl_ + offQKV, nullptr, nullptr,
            qh_, ql_, kh_, kl_, vh_, vl_, cos_, sin_, S, 3 * D, D);

        attn_mma_kernel<<<dim3(S / 64, NH), 128>>>(qh_, ql_, kh_, kl_, vh_, vl_, oh_, ol_);

        gemm_bf16x3_kernel<0><<<GEMM_GRID, 256, SMEM_BYTES>>>(
            oh_, ol_, woh_ + offDD, wol_ + offDD, h_, h_,
            nullptr, nullptr, nullptr, nullptr, nullptr, nullptr, nullptr, nullptr, S, D, D);

        rmsnorm_split_kernel<<<S, 256>>>(h_, fnw + (size_t)l * D, xh_, xl_);

        gemm_bf16x3_kernel<2><<<GEMM_GRID, 256, SMEM_BYTES>>>(
            xh_, xl_, w13h_ + off13, w13l_ + off13, nullptr, nullptr,
            gh_, gl_, nullptr, nullptr, nullptr, nullptr, nullptr, nullptr, S, 2 * HFF, D);

        gemm_bf16x3_kernel<0><<<GEMM_GRID, 256, SMEM_BYTES>>>(
            gh_, gl_, w2h_ + offFD, w2l_ + offFD, h_, h_,
            nullptr, nullptr, nullptr, nullptr, nullptr, nullptr, nullptr, nullptr, S, D, HFF);
    }

    rmsnorm_kernel<<<1, 256>>>(h_ + (size_t)(S - 1) * D, finw, xf_);
    logits_kernel<<<NV / 256, 256>>>(xf_, Wout, out);
}

// round 15
// speedup vs baseline: 1.0887x; 1.0047x over previous
#include <cuda_runtime.h>
#include <cuda_bf16.h>
#include <math.h>
#include <stdint.h>

// ---------------- Problem constants ----------------
#define S    2048
#define D    1024
#define NH   16
#define HD   64
#define HFF  2816
#define NV   32000
#define NL   4

typedef __nv_bfloat16 bf16;

// ---------------- Device scratch ----------------
__device__ float g_h[S * D];
__device__ float g_cos[S * 32];
__device__ float g_sin[S * 32];
__device__ float g_xf[D];

__device__ __align__(16) bf16 g_xh[S * D],  g_xl[S * D];
__device__ __align__(16) bf16 g_oh[S * D],  g_ol[S * D];
__device__ __align__(16) bf16 g_gh[S * HFF], g_gl[S * HFF];
__device__ __align__(16) bf16 g_qh[S * D], g_ql[S * D];
__device__ __align__(16) bf16 g_kh[S * D], g_kl[S * D];
__device__ __align__(16) bf16 g_vh[S * D], g_vl[S * D];

__device__ __align__(16) bf16 g_wqkvh[NL * D * 3 * D], g_wqkvl[NL * D * 3 * D];
__device__ __align__(16) bf16 g_w13h[NL * D * 2 * HFF], g_w13l[NL * D * 2 * HFF];
__device__ __align__(16) bf16 g_woh[NL * D * D], g_wol[NL * D * D];
__device__ __align__(16) bf16 g_w2h[NL * HFF * D], g_w2l[NL * HFF * D];

// ---------------- small helpers ----------------
__device__ __forceinline__ void split1(float v, bf16& h, bf16& l) {
    h = __float2bfloat16(v);
    l = __float2bfloat16(v - __bfloat162float(h));
}
__device__ __forceinline__ void split2pack(float x, float y, unsigned& hp, unsigned& lp) {
    bf16 hx = __float2bfloat16(x), hy = __float2bfloat16(y);
    float lx = x - __bfloat162float(hx), ly = y - __bfloat162float(hy);
    bf16 lxb = __float2bfloat16(lx), lyb = __float2bfloat16(ly);
    hp = (unsigned)(*(unsigned short*)&hx) | ((unsigned)(*(unsigned short*)&hy) << 16);
    lp = (unsigned)(*(unsigned short*)&lxb) | ((unsigned)(*(unsigned short*)&lyb) << 16);
}

// ---------------- ONE fused pack+split kernel for all weights ----------------
#define PDD (D * D / 2)
#define PDF (D * HFF / 2)
__global__ void pack_all_kernel(
    const float* __restrict__ Wq, const float* __restrict__ Wk, const float* __restrict__ Wv,
    const float* __restrict__ W1, const float* __restrict__ W3,
    const float* __restrict__ Wo, const float* __restrict__ W2,
    bf16* __restrict__ qkvh, bf16* __restrict__ qkvl,
    bf16* __restrict__ w13h, bf16* __restrict__ w13l,
    bf16* __restrict__ woh, bf16* __restrict__ wol,
    bf16* __restrict__ w2h, bf16* __restrict__ w2l) {
    const int l = blockIdx.z;
    long idx = (long)blockIdx.x * 256 + threadIdx.x;

    if (idx < 3L * PDD) {
        int seg = (int)(idx / PDD);
        int r = (int)(idx % PDD);
        const float* src = (seg == 0 ? Wq : seg == 1 ? Wk : Wv) + (size_t)l * D * D;
        int k = r / (D / 2), n = (r % (D / 2)) * 2;
        float2 v = *(const float2*)(src + (size_t)k * D + n);
        unsigned hp, lp; split2pack(v.x, v.y, hp, lp);
        size_t o = (size_t)l * 3 * D * D + (size_t)k * 3 * D + seg * D + n;
        *(unsigned*)(qkvh + o) = hp;
        *(unsigned*)(qkvl + o) = lp;
        return;
    }
    idx -= 3L * PDD;
    if (idx < 2L * PDF) {
        int seg = (int)(idx / PDF);
        int r = (int)(idx % PDF);
        const float* src = (seg == 0 ? W1 : W3) + (size_t)l * D * HFF;
        int k = r / (HFF / 2), n = (r % (HFF / 2)) * 2;
        float2 v = *(const float2*)(src + (size_t)k * HFF + n);
        bf16 h, lo;
        size_t o = (size_t)l * 2 * D * HFF + (size_t)k * 2 * HFF + seg + 2 * n;
        split1(v.x, h, lo); w13h[o] = h; w13l[o] = lo;
        split1(v.y, h, lo); w13h[o + 2] = h; w13l[o + 2] = lo;
        return;
    }
    idx -= 2L * PDF;
    if (idx < PDD) {
        const float* src = Wo + (size_t)l * D * D;
        int k = (int)(idx / (D / 2)), n = (int)(idx % (D / 2)) * 2;
        float2 v = *(const float2*)(src + (size_t)k * D + n);
        unsigned hp, lp; split2pack(v.x, v.y, hp, lp);
        size_t o = (size_t)l * D * D + (size_t)k * D + n;
        *(unsigned*)(woh + o) = hp;
        *(unsigned*)(wol + o) = lp;
        return;
    }
    idx -= PDD;
    {
        const float* src = W2 + (size_t)l * HFF * D;
        int k = (int)(idx / (D / 2)), n = (int)(idx % (D / 2)) * 2;
        float2 v = *(const float2*)(src + (size_t)k * D + n);
        unsigned hp, lp; split2pack(v.x, v.y, hp, lp);
        size_t o = (size_t)l * HFF * D + (size_t)k * D + n;
        *(unsigned*)(w2h + o) = hp;
        *(unsigned*)(w2l + o) = lp;
    }
}
#define PACK_TOTAL (4L * PDD + 3L * PDF)

// ---------------- RoPE table ----------------
__global__ void rope_table_kernel(float* ct, float* st) {
    int idx = blockIdx.x * 256 + threadIdx.x;
    if (idx >= S * 32) return;
    int pos = idx >> 5;
    int i = idx & 31;
    float inv = powf(10000.0f, -((float)(2 * i) / (float)HD));
    float ang = (float)pos * inv;
    float s, c;
    sincosf(ang, &s, &c);
    ct[idx] = c;
    st[idx] = s;
}

// ---------------- Embedding gather (float4) ----------------
__global__ void embed_kernel(const int* __restrict__ tokens,
                             const float* __restrict__ emb,
                             float* __restrict__ h) {
    int idx = blockIdx.x * 256 + threadIdx.x;      // S*D/4
    int s = idx >> 8;
    int d4 = idx & 255;
    ((float4*)h)[(size_t)s * 256 + d4] =
        ((const float4*)(emb + (size_t)tokens[s] * D))[d4];
}

// ---------------- RMSNorm -> split bf16 hi/lo (vectorized) ----------------
__global__ void rmsnorm_split_kernel(const float* __restrict__ in,
                                     const float* __restrict__ w,
                                     bf16* __restrict__ oh, bf16* __restrict__ ol) {
    const int t = threadIdx.x;
    float4 v = ((const float4*)(in + (size_t)blockIdx.x * D))[t];
    float ss = v.x * v.x + v.y * v.y + v.z * v.z + v.w * v.w;
#pragma unroll
    for (int off = 16; off; off >>= 1) ss += __shfl_xor_sync(0xffffffffu, ss, off);
    __shared__ float red[8];
    if ((t & 31) == 0) red[t >> 5] = ss;
    __syncthreads();
    if (t < 8) {
        float x = red[t];
#pragma unroll
        for (int off = 4; off; off >>= 1) x += __shfl_xor_sync(0xffu, x, off);
        if (t == 0) red[0] = x;
    }
    __syncthreads();
    float scale = rsqrtf(red[0] * (1.0f / (float)D) + 1e-6f);
    float4 wv = ((const float4*)w)[t];
    unsigned h0, l0, h1, l1;
    split2pack(v.x * scale * wv.x, v.y * scale * wv.y, h0, l0);
    split2pack(v.z * scale * wv.z, v.w * scale * wv.w, h1, l1);
    ((uint2*)(oh + (size_t)blockIdx.x * D))[t] = make_uint2(h0, h1);
    ((uint2*)(ol + (size_t)blockIdx.x * D))[t] = make_uint2(l0, l1);
}

// ---------------- plain fp32 RMSNorm (final row, vectorized) ----------------
__global__ void rmsnorm_kernel(const float* __restrict__ in,
                               const float* __restrict__ w,
                               float* __restrict__ out) {
    const int t = threadIdx.x;
    float4 v = ((const float4*)in)[t];
    float ss = v.x * v.x + v.y * v.y + v.z * v.z + v.w * v.w;
#pragma unroll
    for (int off = 16; off; off >>= 1) ss += __shfl_xor_sync(0xffffffffu, ss, off);
    __shared__ float red[8];
    if ((t & 31) == 0) red[t >> 5] = ss;
    __syncthreads();
    if (t < 8) {
        float x = red[t];
#pragma unroll
        for (int off = 4; off; off >>= 1) x += __shfl_xor_sync(0xffu, x, off);
        if (t == 0) red[0] = x;
    }
    __syncthreads();
    float scale = rsqrtf(red[0] * (1.0f / (float)D) + 1e-6f);
    float4 wv = ((const float4*)w)[t];
    ((float4*)out)[t] = make_float4(v.x * scale * wv.x, v.y * scale * wv.y,
                                    v.z * scale * wv.z, v.w * scale * wv.w);
}

// ---------------- MMA helpers ----------------
#define LDSM4(r0, r1, r2, r3, addr)                                          \
    asm volatile("ldmatrix.sync.aligned.m8n8.x4.shared.b16 {%0,%1,%2,%3},[%4];" \
                 : "=r"(r0), "=r"(r1), "=r"(r2), "=r"(r3) : "r"(addr))
#define LDSM4T(r0, r1, r2, r3, addr)                                         \
    asm volatile("ldmatrix.sync.aligned.m8n8.x4.trans.shared.b16 {%0,%1,%2,%3},[%4];" \
                 : "=r"(r0), "=r"(r1), "=r"(r2), "=r"(r3) : "r"(addr))
#define CP_ASYNC16(saddr, gaddr)                                             \
    asm volatile("cp.async.cg.shared.global [%0],[%1],16;" :: "r"(saddr), "l"(gaddr))
#define CP_COMMIT() asm volatile("cp.async.commit_group;" ::: "memory")
#define CP_WAIT2()  asm volatile("cp.async.wait_group 2;" ::: "memory")
#define CP_WAIT0()  asm volatile("cp.async.wait_group 0;" ::: "memory")

__device__ __forceinline__ void mma16816(float* c, const unsigned* a, const unsigned* b) {
    asm volatile(
        "mma.sync.aligned.m16n8k16.row.col.f32.bf16.bf16.f32 "
        "{%0,%1,%2,%3},{%4,%5,%6,%7},{%8,%9},{%0,%1,%2,%3};"
        : "+f"(c[0]), "+f"(c[1]), "+f"(c[2]), "+f"(c[3])
        : "r"(a[0]), "r"(a[1]), "r"(a[2]), "r"(a[3]), "r"(b[0]), "r"(b[1]));
}

// ---------------- bf16x3 GEMM: persistent CTAs, cp.async 4-stage, reg-double-buffered ----------------
#define GBM 128
#define GBN 128
#define GBK 32
#define NSTAGE 4
#define A_BUF_BYTES 10240
#define B_BUF_BYTES 8704
#define A_STAGE_BYTES 20480
#define STAGE_BYTES 37888
#define SMEM_BYTES (NSTAGE * STAGE_BYTES)
#define GEMM_GRID 148

extern __shared__ char gsmem[];

template <int MODE>
__global__ __launch_bounds__(256) void gemm_bf16x3_kernel(
    const bf16* __restrict__ Ah, const bf16* __restrict__ Al,
    const bf16* __restrict__ Bh, const bf16* __restrict__ Bl,
    const float* __restrict__ RES, float* __restrict__ C,
    bf16* __restrict__ O1h, bf16* __restrict__ O1l,
    bf16* __restrict__ O2h, bf16* __restrict__ O2l,
    bf16* __restrict__ O3h, bf16* __restrict__ O3l,
    const float* __restrict__ ct, const float* __restrict__ st,
    int M, int N, int K) {
    const int tid  = threadIdx.x;
    const int warp = tid >> 5;
    const int lane = tid & 31;
    const int wm   = (warp >> 2) * 64;
    const int wn   = (warp & 3) * 32;
    const int grp  = lane >> 3;
    const int rin  = lane & 7;

    const uint32_t sBase = (uint32_t)__cvta_generic_to_shared(gsmem);
    const uint32_t laneA = (uint32_t)((((grp & 1) << 3) + rin) * 80 + ((grp >> 1) << 4));
    const uint32_t laneB = (uint32_t)((((grp & 1) << 3) + rin) * 272 + (((grp >> 1) << 3) + wn) * 2);

    const int KT = K / GBK;
    const int nbn = N / GBN;
    const int tiles = (M / GBM) * nbn;

    int bm, bn;

    auto issue = [&](int kt, int stage) {
        const uint32_t stOff = sBase + stage * STAGE_BYTES;
        const int kOff = kt * GBK;
#pragma unroll
        for (int i = 0; i < 4; i++) {
            int c = tid + 256 * i;
            int buf = c >> 9, rem = c & 511;
            int m = rem >> 2, kq = rem & 3;
            const bf16* g = (buf ? Al : Ah) + (size_t)(bm + m) * K + kOff + kq * 8;
            uint32_t sa = stOff + buf * A_BUF_BYTES + m * 80 + kq * 16;
            CP_ASYNC16(sa, g);
        }
#pragma unroll
        for (int i = 0; i < 4; i++) {
            int c = tid + 256 * i;
            int buf = c >> 9, rem = c & 511;
            int kk = rem >> 4, nq = rem & 15;
            const bf16* g = (buf ? Bl : Bh) + (size_t)(kOff + kk) * N + bn + nq * 8;
            uint32_t sa = stOff + A_STAGE_BYTES + buf * B_BUF_BYTES + kk * 272 + nq * 16;
            CP_ASYNC16(sa, g);
        }
    };

    auto load_frags = [&](unsigned (&a)[2][4][4], unsigned (&b)[2][4][2],
                          uint32_t stOff, int ks) {
#pragma unroll
        for (int buf = 0; buf < 2; buf++) {
            uint32_t aS = stOff + buf * A_BUF_BYTES + laneA + ks * 32;
#pragma unroll
            for (int mt = 0; mt < 4; mt++) {
                uint32_t addr = aS + (wm + mt * 16) * 80;
                LDSM4(a[buf][mt][0], a[buf][mt][1], a[buf][mt][2], a[buf][mt][3], addr);
            }
            uint32_t bS = stOff + A_STAGE_BYTES + buf * B_BUF_BYTES + laneB + ks * 4352;
#pragma unroll
            for (int nj = 0; nj < 2; nj++) {
                uint32_t addr = bS + nj * 32;
                LDSM4T(b[buf][2 * nj][0], b[buf][2 * nj][1],
                       b[buf][2 * nj + 1][0], b[buf][2 * nj + 1][1], addr);
            }
        }
    };

    for (int tile = blockIdx.x; tile < tiles; tile += GEMM_GRID) {
        bm = (tile / nbn) * GBM;
        bn = (tile % nbn) * GBN;

        float acc[4][4][4];
#pragma unroll
        for (int mi = 0; mi < 4; mi++)
#pragma unroll
            for (int ni = 0; ni < 4; ni++)
#pragma unroll
                for (int j = 0; j < 4; j++) acc[mi][ni][j] = 0.f;

        auto do_mma = [&](unsigned (&a)[2][4][4], unsigned (&b)[2][4][2]) {
#pragma unroll
            for (int mt = 0; mt < 4; mt++)
#pragma unroll
                for (int nt = 0; nt < 4; nt++)
                    mma16816(acc[mt][nt], a[0][mt], b[0][nt]);
#pragma unroll
            for (int mt = 0; mt < 4; mt++)
#pragma unroll
                for (int nt = 0; nt < 4; nt++)
                    mma16816(acc[mt][nt], a[0][mt], b[1][nt]);
#pragma unroll
            for (int mt = 0; mt < 4; mt++)
#pragma unroll
                for (int nt = 0; nt < 4; nt++)
                    mma16816(acc[mt][nt], a[1][mt], b[0][nt]);
        };

        unsigned aX[2][4][4], bX[2][4][2];
        unsigned aY[2][4][4], bY[2][4][2];

        issue(0, 0); CP_COMMIT();
        issue(1, 1); CP_COMMIT();
        issue(2, 2); CP_COMMIT();
        CP_WAIT2();
        __syncthreads();
        load_frags(aX, bX, sBase, 0);

        for (int kt = 0; kt < KT; kt++) {
            const uint32_t stOff = sBase + (kt % NSTAGE) * STAGE_BYTES;
            load_frags(aY, bY, stOff, 1);
            do_mma(aX, bX);
            if (kt + 3 < KT) issue(kt + 3, (kt + 3) % NSTAGE);
            CP_COMMIT();
            CP_WAIT2();
            __syncthreads();
            if (kt + 1 < KT)
                load_frags(aX, bX, sBase + ((kt + 1) % NSTAGE) * STAGE_BYTES, 0);
            do_mma(aY, bY);
        }
        CP_WAIT0();
        __syncthreads();

        // ---- fused epilogue ----
        const int r0 = bm + wm + (lane >> 2);
        const int c0 = bn + wn + (lane & 3) * 2;
#pragma unroll
        for (int mt = 0; mt < 4; mt++)
#pragma unroll
            for (int nt = 0; nt < 4; nt++) {
                const int col = c0 + nt * 8;
#pragma unroll
                for (int rp = 0; rp < 2; rp++) {
                    const int row = r0 + mt * 16 + rp * 8;
                    float2 v = make_float2(acc[mt][nt][2 * rp], acc[mt][nt][2 * rp + 1]);
                    if (MODE == 0) {
                        if (RES) {
                            float2 a0 = *(const float2*)(RES + (size_t)row * N + col);
                            v.x += a0.x; v.y += a0.y;
                        }
                        *(float2*)(C + (size_t)row * N + col) = v;
                    } else if (MODE == 1) {
                        const int seg = col >> 10;
                        const int d = col & 1023;
                        if (seg < 2) {
                            const int i = (d & 63) >> 1;
                            float c = ct[row * 32 + i];
                            float s = st[row * 32 + i];
                            float a0 = v.x * c - v.y * s;
                            float b0 = v.x * s + v.y * c;
                            v.x = a0; v.y = b0;
                        }
                        unsigned hp, lp;
                        split2pack(v.x, v.y, hp, lp);
                        bf16* oh = (seg == 0) ? O1h : (seg == 1) ? O2h : O3h;
                        bf16* ol = (seg == 0) ? O1l : (seg == 1) ? O2l : O3l;
                        *(unsigned*)(oh + (size_t)row * D + d) = hp;
                        *(unsigned*)(ol + (size_t)row * D + d) = lp;
                    } else {
                        const int j = col >> 1;
                        float z = v.x;
                        float sig = 1.0f / (1.0f + __expf(-z));
                        float r = z * sig * v.y;
                        bf16 h, l; split1(r, h, l);
                        O1h[(size_t)row * HFF + j] = h;
                        O1l[(size_t)row * HFF + j] = l;
                    }
                }
            }
        __syncthreads();
    }
}

// ---------------- Tensor-core flash attention (Q in smem; regs capped for 3 CTAs/SM) ----------------
#define AP 72   // smem row pitch in halfs (144B)

__global__ __launch_bounds__(128, 3) void attn_mma_kernel(
    const bf16* __restrict__ Qh, const bf16* __restrict__ Ql,
    const bf16* __restrict__ Kh, const bf16* __restrict__ Kl,
    const bf16* __restrict__ Vh, const bf16* __restrict__ Vl,
    bf16* __restrict__ Oh, bf16* __restrict__ Ol) {
    __shared__ __align__(16) bf16 sQ[2][64 * AP];
    __shared__ __align__(16) bf16 sK[2][64 * AP];
    __shared__ __align__(16) bf16 sV[2][64 * AP];

    const int qt   = gridDim.x - 1 - blockIdx.x;   // longest-first
    const int head = blockIdx.y;
    const int tid  = threadIdx.x;
    const int warp = tid >> 5;
    const int lane = tid & 31;
    const int grp  = lane >> 3;
    const int rin  = lane & 7;
    const int wq   = warp * 16;

    {
        const bf16* qsrc[2] = {Qh, Ql};
#pragma unroll
        for (int c = tid; c < 1024; c += 128) {
            int buf = c >> 9, rem = c & 511;
            int row = rem >> 3, col8 = rem & 7;
            *(uint4*)&sQ[buf][row * AP + col8 * 8] =
                *(const uint4*)(qsrc[buf] + (size_t)(qt * 64 + row) * D + head * HD + col8 * 8);
        }
    }

    float o[8][4];
#pragma unroll
    for (int nt = 0; nt < 8; nt++)
#pragma unroll
        for (int j = 0; j < 4; j++) o[nt][j] = 0.f;
    float m0 = -1e30f, m1 = -1e30f, l0 = 0.f, l1 = 0.f;
    const float scale = 0.125f;

    const uint32_t sQ0 = (uint32_t)__cvta_generic_to_shared(&sQ[0][0]);
    const uint32_t sQ1 = (uint32_t)__cvta_generic_to_shared(&sQ[1][0]);
    const uint32_t sK0 = (uint32_t)__cvta_generic_to_shared(&sK[0][0]);
    const uint32_t sK1 = (uint32_t)__cvta_generic_to_shared(&sK[1][0]);
    const uint32_t sV0 = (uint32_t)__cvta_generic_to_shared(&sV[0][0]);
    const uint32_t sV1 = (uint32_t)__cvta_generic_to_shared(&sV[1][0]);
    const uint32_t laneOffQ = (uint32_t)(((wq + ((grp & 1) << 3) + rin) * AP + ((grp >> 1) << 3)) << 1);

    const int r0g = qt * 64 + wq + (lane >> 2);
    const int r1g = r0g + 8;

    for (int kt = 0; kt <= qt; kt++) {
        __syncthreads();
        {
            const bf16* src[4] = {Kh, Kl, Vh, Vl};
            bf16* dst[4] = {sK[0], sK[1], sV[0], sV[1]};
#pragma unroll
            for (int c = tid; c < 2048; c += 128) {
                int which = c >> 9, rem = c & 511;
                int row = rem >> 3, col8 = rem & 7;
                *(uint4*)&dst[which][row * AP + col8 * 8] =
                    *(const uint4*)(src[which] + (size_t)(kt * 64 + row) * D + head * HD + col8 * 8);
            }
        }
        __syncthreads();

        unsigned aQ[2][4][4];
#pragma unroll
        for (int kc = 0; kc < 4; kc++) {
            LDSM4(aQ[0][kc][0], aQ[0][kc][1], aQ[0][kc][2], aQ[0][kc][3], sQ0 + laneOffQ + kc * 32);
            LDSM4(aQ[1][kc][0], aQ[1][kc][1], aQ[1][kc][2], aQ[1][kc][3], sQ1 + laneOffQ + kc * 32);
        }

        float s[8][4];
#pragma unroll
        for (int nt = 0; nt < 8; nt++)
#pragma unroll
            for (int j = 0; j < 4; j++) s[nt][j] = 0.f;

#pragma unroll
        for (int kc = 0; kc < 4; kc++) {
            unsigned bh[8][2], bl[8][2];
#pragma unroll
            for (int np = 0; np < 4; np++) {
                uint32_t off = (uint32_t)(((np * 16 + ((grp >> 1) << 3) + rin) * AP
                                           + kc * 16 + ((grp & 1) << 3)) << 1);
                LDSM4(bh[2 * np][0], bh[2 * np][1], bh[2 * np + 1][0], bh[2 * np + 1][1], sK0 + off);
                LDSM4(bl[2 * np][0], bl[2 * np][1], bl[2 * np + 1][0], bl[2 * np + 1][1], sK1 + off);
            }
#pragma unroll
            for (int nt = 0; nt < 8; nt++) mma16816(s[nt], aQ[0][kc], bh[nt]);
#pragma unroll
            for (int nt = 0; nt < 8; nt++) mma16816(s[nt], aQ[0][kc], bl[nt]);
#pragma unroll
            for (int nt = 0; nt < 8; nt++) mma16816(s[nt], aQ[1][kc], bh[nt]);
        }

        const bool diag = (kt == qt);
#pragma unroll
        for (int nt = 0; nt < 8; nt++) {
            int c0g = kt * 64 + nt * 8 + (lane & 3) * 2;
            s[nt][0] *= scale; s[nt][1] *= scale;
            s[nt][2] *= scale; s[nt][3] *= scale;
            if (diag) {
                if (c0g     > r0g) s[nt][0] = -1e30f;
                if (c0g + 1 > r0g) s[nt][1] = -1e30f;
                if (c0g     > r1g) s[nt][2] = -1e30f;
                if (c0g + 1 > r1g) s[nt][3] = -1e30f;
            }
        }

        float mx0 = -1e30f, mx1 = -1e30f;
#pragma unroll
        for (int nt = 0; nt < 8; nt++) {
            mx0 = fmaxf(mx0, fmaxf(s[nt][0], s[nt][1]));
            mx1 = fmaxf(mx1, fmaxf(s[nt][2], s[nt][3]));
        }
        mx0 = fmaxf(mx0, __shfl_xor_sync(0xffffffffu, mx0, 1));
        mx0 = fmaxf(mx0, __shfl_xor_sync(0xffffffffu, mx0, 2));
        mx1 = fmaxf(mx1, __shfl_xor_sync(0xffffffffu, mx1, 1));
        mx1 = fmaxf(mx1, __shfl_xor_sync(0xffffffffu, mx1, 2));
        float mn0 = fmaxf(m0, mx0), mn1 = fmaxf(m1, mx1);
        float cr0 = __expf(m0 - mn0), cr1 = __expf(m1 - mn1);
        m0 = mn0; m1 = mn1;
        float rs0 = 0.f, rs1 = 0.f;
#pragma unroll
        for (int nt = 0; nt < 8; nt++) {
            s[nt][0] = __expf(s[nt][0] - mn0); rs0 += s[nt][0];
            s[nt][1] = __expf(s[nt][1] - mn0); rs0 += s[nt][1];
            s[nt][2] = __expf(s[nt][2] - mn1); rs1 += s[nt][2];
            s[nt][3] = __expf(s[nt][3] - mn1); rs1 += s[nt][3];
        }
        l0 = l0 * cr0 + rs0;
        l1 = l1 * cr1 + rs1;
#pragma unroll
        for (int nt = 0; nt < 8; nt++) {
            o[nt][0] *= cr0; o[nt][1] *= cr0;
            o[nt][2] *= cr1; o[nt][3] *= cr1;
        }

#pragma unroll
        for (int kc = 0; kc < 4; kc++) {
            int t0 = 2 * kc, t1 = 2 * kc + 1;
            unsigned ah[4], al[4];
            split2pack(s[t0][0], s[t0][1], ah[0], al[0]);
            split2pack(s[t0][2], s[t0][3], ah[1], al[1]);
            split2pack(s[t1][0], s[t1][1], ah[2], al[2]);
            split2pack(s[t1][2], s[t1][3], ah[3], al[3]);

            unsigned bvh[8][2], bvl[8][2];
#pragma unroll
            for (int np = 0; np < 4; np++) {
                uint32_t off = (uint32_t)(((kc * 16 + ((grp & 1) << 3) + rin) * AP
                                           + np * 16 + ((grp >> 1) << 3)) << 1);
                LDSM4T(bvh[2 * np][0], bvh[2 * np][1], bvh[2 * np + 1][0], bvh[2 * np + 1][1], sV0 + off);
                LDSM4T(bvl[2 * np][0], bvl[2 * np][1], bvl[2 * np + 1][0], bvl[2 * np + 1][1], sV1 + off);
            }
#pragma unroll
            for (int nt = 0; nt < 8; nt++) mma16816(o[nt], ah, bvh[nt]);
#pragma unroll
            for (int nt = 0; nt < 8; nt++) mma16816(o[nt], ah, bvl[nt]);
#pragma unroll
            for (int nt = 0; nt < 8; nt++) mma16816(o[nt], al, bvh[nt]);
        }
    }

    l0 += __shfl_xor_sync(0xffffffffu, l0, 1);
    l0 += __shfl_xor_sync(0xffffffffu, l0, 2);
    l1 += __shfl_xor_sync(0xffffffffu, l1, 1);
    l1 += __shfl_xor_sync(0xffffffffu, l1, 2);
    float inv0 = 1.f / l0, inv1 = 1.f / l1;
#pragma unroll
    for (int nt = 0; nt < 8; nt++) {
        int col = head * HD + nt * 8 + (lane & 3) * 2;
        unsigned hp, lp;
        split2pack(o[nt][0] * inv0, o[nt][1] * inv0, hp, lp);
        *(unsigned*)(Oh + (size_t)r0g * D + col) = hp;
        *(unsigned*)(Ol + (size_t)r0g * D + col) = lp;
        split2pack(o[nt][2] * inv1, o[nt][3] * inv1, hp, lp);
        *(unsigned*)(Oh + (size_t)r1g * D + col) = hp;
        *(unsigned*)(Ol + (size_t)r1g * D + col) = lp;
    }
}

// ---------------- Logits ----------------
__global__ void logits_kernel(const float* __restrict__ xf,
                              const float* __restrict__ Wout,
                              float* __restrict__ out) {
    __shared__ float xs[D];
    for (int i = threadIdx.x; i < D; i += 256) xs[i] = xf[i];
    __syncthreads();
    int v = blockIdx.x * 256 + threadIdx.x;
    float acc = 0.f;
#pragma unroll 8
    for (int d = 0; d < D; d++) acc += xs[d] * Wout[(size_t)d * NV + v];
    out[v] = acc;
}

// ---------------- Host launch ----------------
extern "C" void kernel_launch(void* const* d_in, const int* in_sizes, int n_in,
                              void* d_out, int out_size) {
    int bi = 1;
    if (n_in >= 2 && in_sizes[1] == 1) bi = 2;
    const int*   tokens  = (const int*)d_in[0];
    const float* tok_emb = (const float*)d_in[bi + 0];
    const float* Wq      = (const float*)d_in[bi + 1];
    const float* Wk      = (const float*)d_in[bi + 2];
    const float* Wv      = (const float*)d_in[bi + 3];
    const float* Wo      = (const float*)d_in[bi + 4];
    const float* W1      = (const float*)d_in[bi + 5];
    const float* W2      = (const float*)d_in[bi + 6];
    const float* W3      = (const float*)d_in[bi + 7];
    const float* anw     = (const float*)d_in[bi + 8];
    const float* fnw     = (const float*)d_in[bi + 9];
    const float* finw    = (const float*)d_in[bi + 10];
    const float* Wout    = (const float*)d_in[bi + 11];
    float* out = (float*)d_out;

    float *h_, *cos_, *sin_, *xf_;
    bf16 *xh_, *xl_, *oh_, *ol_, *gh_, *gl_;
    bf16 *qh_, *ql_, *kh_, *kl_, *vh_, *vl_;
    bf16 *wqkvh_, *wqkvl_, *w13h_, *w13l_, *woh_, *wol_, *w2h_, *w2l_;

    cudaGetSymbolAddress((void**)&h_,  g_h);
    cudaGetSymbolAddress((void**)&cos_, g_cos);
    cudaGetSymbolAddress((void**)&sin_, g_sin);
    cudaGetSymbolAddress((void**)&xf_, g_xf);
    cudaGetSymbolAddress((void**)&xh_, g_xh);
    cudaGetSymbolAddress((void**)&xl_, g_xl);
    cudaGetSymbolAddress((void**)&oh_, g_oh);
    cudaGetSymbolAddress((void**)&ol_, g_ol);
    cudaGetSymbolAddress((void**)&gh_, g_gh);
    cudaGetSymbolAddress((void**)&gl_, g_gl);
    cudaGetSymbolAddress((void**)&qh_, g_qh); cudaGetSymbolAddress((void**)&ql_, g_ql);
    cudaGetSymbolAddress((void**)&kh_, g_kh); cudaGetSymbolAddress((void**)&kl_, g_kl);
    cudaGetSymbolAddress((void**)&vh_, g_vh); cudaGetSymbolAddress((void**)&vl_, g_vl);
    cudaGetSymbolAddress((void**)&wqkvh_, g_wqkvh); cudaGetSymbolAddress((void**)&wqkvl_, g_wqkvl);
    cudaGetSymbolAddress((void**)&w13h_, g_w13h); cudaGetSymbolAddress((void**)&w13l_, g_w13l);
    cudaGetSymbolAddress((void**)&woh_, g_woh); cudaGetSymbolAddress((void**)&wol_, g_wol);
    cudaGetSymbolAddress((void**)&w2h_, g_w2h); cudaGetSymbolAddress((void**)&w2l_, g_w2l);

    static int smem_set = 0;
    if (!smem_set) {
        cudaFuncSetAttribute(gemm_bf16x3_kernel<0>,
                             cudaFuncAttributeMaxDynamicSharedMemorySize, SMEM_BYTES);
        cudaFuncSetAttribute(gemm_bf16x3_kernel<1>,
                             cudaFuncAttributeMaxDynamicSharedMemorySize, SMEM_BYTES);
        cudaFuncSetAttribute(gemm_bf16x3_kernel<2>,
                             cudaFuncAttributeMaxDynamicSharedMemorySize, SMEM_BYTES);
        smem_set = 1;
    }

    {
        dim3 grid((unsigned)(PACK_TOTAL / 256), 1, NL);
        pack_all_kernel<<<grid, 256>>>(Wq, Wk, Wv, W1, W3, Wo, W2,
                                       wqkvh_, wqkvl_, w13h_, w13l_,
                                       woh_, wol_, w2h_, w2l_);
    }

    rope_table_kernel<<<(S * 32 + 255) / 256, 256>>>(cos_, sin_);
    embed_kernel<<<(S * D / 4) / 256, 256>>>(tokens, tok_emb, h_);

    for (int l = 0; l < NL; l++) {
        size_t offQKV = (size_t)l * 3 * D * D;
        size_t offDD  = (size_t)l * D * D;
        size_t off13  = (size_t)l * 2 * D * HFF;
        size_t offFD  = (size_t)l * HFF * D;

        rmsnorm_split_kernel<<<S, 256>>>(h_, anw + (size_t)l * D, xh_, xl_);

        gemm_bf16x3_kernel<1><<<GEMM_GRID, 256, SMEM_BYTES>>>(
            xh_, xl_, wqkvh_ + offQKV, wqkvl_ + offQKV, nullptr, nullptr,
            qh_, ql_, kh_, kl_, vh_, vl_, cos_, sin_, S, 3 * D, D);

        attn_mma_kernel<<<dim3(S / 64, NH), 128>>>(qh_, ql_, kh_, kl_, vh_, vl_, oh_, ol_);

        gemm_bf16x3_kernel<0><<<GEMM_GRID, 256, SMEM_BYTES>>>(
            oh_, ol_, woh_ + offDD, wol_ + offDD, h_, h_,
            nullptr, nullptr, nullptr, nullptr, nullptr, nullptr, nullptr, nullptr, S, D, D);

        rmsnorm_split_kernel<<<S, 256>>>(h_, fnw + (size_t)l * D, xh_, xl_);

        gemm_bf16x3_kernel<2><<<GEMM_GRID, 256, SMEM_BYTES>>>(
            xh_, xl_, w13h_ + off13, w13l_ + off13, nullptr, nullptr,
            gh_, gl_, nullptr, nullptr, nullptr, nullptr, nullptr, nullptr, S, 2 * HFF, D);

        gemm_bf16x3_kernel<0><<<GEMM_GRID, 256, SMEM_BYTES>>>(
            gh_, gl_, w2h_ + offFD, w2l_ + offFD, h_, h_,
            nullptr, nullptr, nullptr, nullptr, nullptr, nullptr, nullptr, nullptr, S, D, HFF);
    }

    rmsnorm_kernel<<<1, 256>>>(h_ + (size_t)(S - 1) * D, finw, xf_);
    logits_kernel<<<NV / 256, 256>>>(xf_, Wout, out);
}